// round 2
// baseline (speedup 1.0000x reference)
#include <cuda_runtime.h>
#include <cuda_fp16.h>
#include <math.h>

#define BB  128   // batch
#define TT  512   // time
#define II  300   // input dim
#define HH  150   // hidden per dir
#define G3  450   // 3*H
#define KK  6     // topics
#define CC  300   // attn context dim
#define THD 20    // topic hidden
#define NCLS 5
#define D2  300   // 2*H

// ---------------- scratch (device globals; no allocations allowed) ----------
__device__ float g_gi[2][TT][BB][G3];     // input projections, [dir][t][b][3H]
__device__ float g_seq[BB][TT][D2];       // bi-GRU outputs
__device__ float g_hidden[BB][D2];        // final hidden states
__device__ float g_ctxbase[KK][D2];       // batch-independent part of context
__device__ float g_context[BB][KK][D2];   // tanh context
__device__ float g_regpart[BB];

// ======================= K1: gi = x @ Wih^T + bih ===========================
// Tile: BM=128 rows (= all 128 batch rows of one t), BN=96 cols, BK=20.
// grid = (ceil(450/96)=5, 512, 2 dirs), 256 threads, 8x6 micro-tile/thread.
#define BM 128
#define BN 96
#define BK 20
__global__ void k_gi(const float* __restrict__ x,
                     const float* __restrict__ Wf, const float* __restrict__ bf,
                     const float* __restrict__ Wb, const float* __restrict__ bb)
{
    int dir = blockIdx.z;
    int t   = blockIdx.y;
    int n0  = blockIdx.x * BN;
    const float* Wih = dir ? Wb : Wf;
    const float* bih = dir ? bb : bf;
    int t_eff = dir ? (TT - 1 - t) : t;

    __shared__ float As[BK][BM + 1];   // +1 pad: kill STS bank conflicts
    __shared__ float Bs[BK][BN + 1];

    int tid = threadIdx.x;
    int tx = tid & 15;      // 16 cols of threads
    int ty = tid >> 4;      // 16 rows of threads
    // thread covers rows b = ty + 16*r (r<8), cols j = n0 + tx + 16*c (c<6)

    float acc[8][6];
#pragma unroll
    for (int r = 0; r < 8; r++)
#pragma unroll
        for (int c = 0; c < 6; c++) acc[r][c] = 0.f;

    for (int k0 = 0; k0 < II; k0 += BK) {
        for (int idx = tid; idx < BM * BK; idx += 256) {
            int b  = idx / BK, kk = idx % BK;
            As[kk][b] = x[((long)b * TT + t_eff) * II + k0 + kk];
        }
        for (int idx = tid; idx < BN * BK; idx += 256) {
            int j = idx / BK, kk = idx % BK;
            int jj = n0 + j;
            Bs[kk][j] = (jj < G3) ? Wih[(long)jj * II + k0 + kk] : 0.f;
        }
        __syncthreads();
#pragma unroll
        for (int kk = 0; kk < BK; kk++) {
            float a[8], bv[6];
#pragma unroll
            for (int r = 0; r < 8; r++) a[r] = As[kk][ty + 16 * r];
#pragma unroll
            for (int c = 0; c < 6; c++) bv[c] = Bs[kk][tx + 16 * c];
#pragma unroll
            for (int r = 0; r < 8; r++)
#pragma unroll
                for (int c = 0; c < 6; c++) acc[r][c] = fmaf(a[r], bv[c], acc[r][c]);
        }
        __syncthreads();
    }
#pragma unroll
    for (int r = 0; r < 8; r++) {
        int b = ty + 16 * r;
#pragma unroll
        for (int c = 0; c < 6; c++) {
            int j = n0 + tx + 16 * c;
            if (j < G3) g_gi[dir][t][b][j] = acc[r][c] + bih[j];
        }
    }
}

// ======================= K2: GRU recurrence =================================
// 128 CTAs: blockIdx.x = dir*64 + pair; each CTA owns 2 batch rows, one dir.
// Whh cached in shared as fp16 (135 KB), fp32 accumulation. 480 threads.
// Per step: threads 0..449 compute gh[j] for both rows; threads 0..299 do gates.
__global__ void k_rec(const float* __restrict__ Whh_f, const float* __restrict__ bhh_f,
                      const float* __restrict__ Whh_b, const float* __restrict__ bhh_b)
{
    extern __shared__ char smem[];
    half2* sW   = (half2*)smem;                        // 450*75 half2 = 135000 B
    float* sbhh = (float*)(smem + 135000);             // 456 floats
    float* sh   = sbhh + 456;                          // 2 * 152 (h state, fp32)
    float* sgh  = sh + 2 * 152;                        // 2 * 452 (pre-activations)
    float* sgin = sgh + 2 * 452;                       // 2 * 152 (gi_n parts)

    int tid  = threadIdx.x;
    int blk  = blockIdx.x;
    int dir  = blk >> 6;
    int pair = blk & 63;
    int b0   = pair * 2;
    const float* Whh = dir ? Whh_b : Whh_f;
    const float* bhh = dir ? bhh_b : bhh_f;

    for (int idx = tid; idx < G3 * 75; idx += blockDim.x) {
        int j = idx / 75, kk = idx % 75;
        sW[j * 75 + kk] = __floats2half2_rn(Whh[j * HH + 2 * kk], Whh[j * HH + 2 * kk + 1]);
    }
    for (int idx = tid; idx < G3; idx += blockDim.x) sbhh[idx] = bhh[idx];
    if (tid < 2 * HH) { int b = tid / HH, jj = tid % HH; sh[b * 152 + jj] = 0.f; }
    __syncthreads();

    const float* gi_base = &g_gi[dir][0][0][0];
    for (int t = 0; t < TT; t++) {
        if (tid < G3) {
            int j = tid;
            long off = ((long)t * BB + b0) * G3 + j;
            float gA = gi_base[off];
            float gB = gi_base[off + G3];
            const half2* wr = sW + j * 75;
            const float2* h0 = (const float2*)(sh);
            const float2* h1 = (const float2*)(sh + 152);
            float acc0 = sbhh[j], acc1 = acc0;
#pragma unroll 15
            for (int kk = 0; kk < 75; kk++) {
                float2 w  = __half22float2(wr[kk]);
                float2 p0 = h0[kk];
                float2 p1 = h1[kk];
                acc0 = fmaf(w.x, p0.x, acc0);
                acc0 = fmaf(w.y, p0.y, acc0);
                acc1 = fmaf(w.x, p1.x, acc1);
                acc1 = fmaf(w.y, p1.y, acc1);
            }
            if (j < 2 * HH) {           // r,z gates: gi adds directly
                sgh[j]       = acc0 + gA;
                sgh[452 + j] = acc1 + gB;
            } else {                    // n gate: r scales only the gh part
                sgh[j]       = acc0;
                sgh[452 + j] = acc1;
                sgin[j - 2 * HH]       = gA;
                sgin[152 + j - 2 * HH] = gB;
            }
        }
        __syncthreads();
        if (tid < 2 * HH) {
            int b = tid / HH, jj = tid % HH;
            float* ghb = sgh + b * 452;
            float r = 1.f / (1.f + expf(-ghb[jj]));
            float z = 1.f / (1.f + expf(-ghb[jj + HH]));
            float n = tanhf(sgin[b * 152 + jj] + r * ghb[jj + 2 * HH]);
            float hp = sh[b * 152 + jj];
            float hn = (1.f - z) * n + z * hp;
            sh[b * 152 + jj] = hn;
            int tw = dir ? (TT - 1 - t) : t;
            g_seq[b0 + b][tw][dir * HH + jj] = hn;
        }
        __syncthreads();
    }
    if (tid < 2 * HH) {
        int b = tid / HH, jj = tid % HH;
        g_hidden[b0 + b][dir * HH + jj] = sh[b * 152 + jj];
    }
}

// ============== K3a: batch-independent part of attention context ============
__global__ void k_ctxbase(const float* __restrict__ ac, const float* __restrict__ Wattn,
                          const float* __restrict__ battn)
{
    int k = blockIdx.x;
    __shared__ float sac[CC];
    int tid = threadIdx.x;
    if (tid < CC) sac[tid] = ac[k * CC + tid];
    __syncthreads();
    if (tid < D2) {
        float acc = battn[k * D2 + tid];
        const float* W = Wattn + (long)k * (CC + D2) * D2 + tid;
        for (int c = 0; c < CC; c++) acc = fmaf(sac[c], W[(long)c * D2], acc);
        g_ctxbase[k][tid] = acc;
    }
}

// ============== K3b: context = tanh(base + hidden @ Wattn[:,C:,:]) ==========
__global__ void k_context(const float* __restrict__ Wattn)
{
    int k = blockIdx.x, b = blockIdx.y;
    __shared__ float shid[D2];
    int tid = threadIdx.x;
    if (tid < D2) shid[tid] = g_hidden[b][tid];
    __syncthreads();
    if (tid < D2) {
        float acc = g_ctxbase[k][tid];
        const float* W = Wattn + ((long)k * (CC + D2) + CC) * D2 + tid;
        for (int e = 0; e < D2; e++) acc = fmaf(shid[e], W[(long)e * D2], acc);
        g_context[b][k][tid] = tanhf(acc);
    }
}

// ============== K3c: fused attention + topic + classifier + reg part ========
#define TS 16
__global__ void k_attn(const float* __restrict__ Wtop, const float* __restrict__ btop,
                       const float* __restrict__ Wout, const float* __restrict__ bout,
                       float* __restrict__ out)
{
    int b = blockIdx.x;
    __shared__ float sctx[KK][D2];     // 7200 B
    __shared__ float sE[TT][KK];       // 12288 B (energy -> probs in place)
    __shared__ float sSeq[TS][D2];     // 19200 B
    __shared__ float spool[KK][D2];    // 7200 B
    __shared__ float sfeat[KK * THD];  // 480 B
    __shared__ float sred[256];
    __shared__ float snorm[KK];
    __shared__ float slog[NCLS];
    int tid = threadIdx.x;

    for (int i = tid; i < KK * D2; i += 256) sctx[i / D2][i % D2] = g_context[b][i / D2][i % D2];
    __syncthreads();

    // pass 1: energies
    for (int tile = 0; tile < TT / TS; tile++) {
        int t0 = tile * TS;
        for (int i = tid; i < TS * D2; i += 256)
            sSeq[i / D2][i % D2] = g_seq[b][t0 + i / D2][i % D2];
        __syncthreads();
        if (tid < TS * KK) {
            int r = tid / KK, k = tid % KK;
            float acc = 0.f;
            for (int d = 0; d < D2; d++) acc = fmaf(sSeq[r][d], sctx[k][d], acc);
            sE[t0 + r][k] = acc;
        }
        __syncthreads();
    }

    // softmax over t per k
    for (int k = 0; k < KK; k++) {
        float m = -1e30f;
        for (int t = tid; t < TT; t += 256) m = fmaxf(m, sE[t][k]);
        sred[tid] = m; __syncthreads();
        for (int s = 128; s > 0; s >>= 1) { if (tid < s) sred[tid] = fmaxf(sred[tid], sred[tid + s]); __syncthreads(); }
        m = sred[0]; __syncthreads();
        float sum = 0.f;
        for (int t = tid; t < TT; t += 256) { float e = expf(sE[t][k] - m); sE[t][k] = e; sum += e; }
        sred[tid] = sum; __syncthreads();
        for (int s = 128; s > 0; s >>= 1) { if (tid < s) sred[tid] += sred[tid + s]; __syncthreads(); }
        float inv = 1.f / sred[0]; __syncthreads();
        for (int t = tid; t < TT; t += 256) sE[t][k] *= inv;
        __syncthreads();
    }

    // pass 2: pooled[k][d] = sum_t seq[t][d] * probs[t][k]
    float pacc[8];
#pragma unroll
    for (int i = 0; i < 8; i++) pacc[i] = 0.f;
    for (int tile = 0; tile < TT / TS; tile++) {
        int t0 = tile * TS;
        for (int i = tid; i < TS * D2; i += 256)
            sSeq[i / D2][i % D2] = g_seq[b][t0 + i / D2][i % D2];
        __syncthreads();
#pragma unroll
        for (int i = 0; i < 8; i++) {
            int idx = tid + i * 256;
            if (idx < KK * D2) {
                int k = idx / D2, d = idx % D2;
                float a = pacc[i];
#pragma unroll
                for (int r = 0; r < TS; r++) a = fmaf(sSeq[r][d], sE[t0 + r][k], a);
                pacc[i] = a;
            }
        }
        __syncthreads();
    }
#pragma unroll
    for (int i = 0; i < 8; i++) {
        int idx = tid + i * 256;
        if (idx < KK * D2) spool[idx / D2][idx % D2] = pacc[i];
    }
    __syncthreads();

    // topic (relu) + context row norms (disjoint thread ranges)
    if (tid < KK * THD) {
        int k = tid / THD, hh = tid % THD;
        float acc = btop[k * THD + hh];
        const float* W = Wtop + ((long)k * D2) * THD + hh;
        for (int d = 0; d < D2; d++) acc = fmaf(spool[k][d], W[d * THD], acc);
        sfeat[tid] = fmaxf(acc, 0.f);
    }
    if (tid >= 128 && tid < 128 + KK) {
        int k = tid - 128;
        float s = 0.f;
        for (int d = 0; d < D2; d++) { float v = sctx[k][d]; s = fmaf(v, v, s); }
        snorm[k] = fmaxf(sqrtf(s), 1e-12f);
    }
    __syncthreads();

    // logits
    if (tid < NCLS) {
        float acc = bout[tid];
        for (int f = 0; f < KK * THD; f++) acc = fmaf(sfeat[f], Wout[f * NCLS + tid], acc);
        slog[tid] = acc;
    }
    // reg Gram matrix terms
    if (tid < 64) sred[tid] = 0.f;
    __syncthreads();
    if (tid < KK * KK) {
        int k = tid / KK, j = tid % KK;
        float acc = 0.f;
        for (int d = 0; d < D2; d++) acc = fmaf(sctx[k][d], sctx[j][d], acc);
        acc = acc / (snorm[k] * snorm[j]) - ((k == j) ? 1.f : 0.f);
        sred[tid] = acc * acc;
    }
    __syncthreads();
    if (tid == 0) {
        float m = slog[0];
        for (int c = 1; c < NCLS; c++) m = fmaxf(m, slog[c]);
        float s = 0.f, e[NCLS];
        for (int c = 0; c < NCLS; c++) { e[c] = expf(slog[c] - m); s += e[c]; }
        for (int c = 0; c < NCLS; c++) out[b * NCLS + c] = e[c] / s;
        float rs = 0.f;
        for (int i = 0; i < KK * KK; i++) rs += sred[i];
        g_regpart[b] = sqrtf(rs);
    }
}

// ============== K3d: reg = mean_b regpart =================================
__global__ void k_reg(float* __restrict__ out)
{
    __shared__ float sr[BB];
    int tid = threadIdx.x;
    sr[tid] = g_regpart[tid];
    __syncthreads();
    for (int s = 64; s > 0; s >>= 1) { if (tid < s) sr[tid] += sr[tid + s]; __syncthreads(); }
    if (tid == 0) out[BB * NCLS] = sr[0] / (float)BB;
}

// ===========================================================================
extern "C" void kernel_launch(void* const* d_in, const int* in_sizes, int n_in,
                              void* d_out, int out_size)
{
    const float* x      = (const float*)d_in[0];
    const float* Wih_f  = (const float*)d_in[1];
    const float* Whh_f  = (const float*)d_in[2];
    const float* bih_f  = (const float*)d_in[3];
    const float* bhh_f  = (const float*)d_in[4];
    const float* Wih_b  = (const float*)d_in[5];
    const float* Whh_b  = (const float*)d_in[6];
    const float* bih_b  = (const float*)d_in[7];
    const float* bhh_b  = (const float*)d_in[8];
    const float* ac     = (const float*)d_in[9];
    const float* Wattn  = (const float*)d_in[10];
    const float* battn  = (const float*)d_in[11];
    const float* Wtop   = (const float*)d_in[12];
    const float* btop   = (const float*)d_in[13];
    const float* Wout   = (const float*)d_in[14];
    const float* bout   = (const float*)d_in[15];
    float* out = (float*)d_out;

    cudaFuncSetAttribute(k_rec, cudaFuncAttributeMaxDynamicSharedMemorySize, 146 * 1024);

    dim3 g1(5, TT, 2);
    k_gi<<<g1, 256>>>(x, Wih_f, bih_f, Wih_b, bih_b);
    k_rec<<<128, 480, 142872>>>(Whh_f, bhh_f, Whh_b, bhh_b);
    k_ctxbase<<<KK, 320>>>(ac, Wattn, battn);
    k_context<<<dim3(KK, BB), 320>>>(Wattn);
    k_attn<<<BB, 256>>>(Wtop, btop, Wout, bout, out);
    k_reg<<<1, BB>>>(out);
}

// round 5
// speedup vs baseline: 1.6073x; 1.6073x over previous
#include <cuda_runtime.h>
#include <cuda_fp16.h>
#include <math.h>
#include <stdint.h>

#define BB  128   // batch
#define TT  512   // time
#define II  300   // input dim
#define HH  150   // hidden per dir
#define G3  450   // 3*H
#define KK  6     // topics
#define CC  300   // attn context dim
#define THD 20    // topic hidden
#define NCLS 5
#define D2  300   // 2*H

#define MM    (BB*TT)   // 65536 GEMM rows
#define KPAD  320       // K padded
#define NPAD  1024      // 2 dirs x 512 padded cols

// ---------------- scratch (device globals; no allocations allowed) ----------
__device__ float g_gi[2][TT][BB][G3];     // input projections, [dir][t][b][3H]
__device__ float g_seq[BB][TT][D2];       // bi-GRU outputs
__device__ float g_hidden[BB][D2];        // final hidden states
__device__ float g_ctxbase[KK][D2];       // batch-independent part of context
__device__ float g_context[BB][KK][D2];   // tanh context
__device__ float g_regpart[BB];
__device__ __half g_xh[(size_t)MM * KPAD];   // fp16 x, padded (40 MB)
__device__ __half g_wp[(size_t)NPAD * KPAD]; // fp16 Wih both dirs, padded
__device__ float  g_bihp[NPAD];              // padded bias (both dirs)

// ===================== PTX helpers ==========================================
__device__ __forceinline__ uint32_t smem_u32(const void* p) {
    uint32_t a;
    asm("{ .reg .u64 t; cvta.to.shared.u64 t, %1; cvt.u32.u64 %0, t; }" : "=r"(a) : "l"(p));
    return a;
}
__device__ __forceinline__ void cpasync16(uint32_t dst, const void* src) {
    asm volatile("cp.async.cg.shared.global [%0], [%1], 16;" :: "r"(dst), "l"(src));
}
__device__ __forceinline__ void cp_commit() { asm volatile("cp.async.commit_group;" ::: "memory"); }
__device__ __forceinline__ void cp_wait1()  { asm volatile("cp.async.wait_group 1;" ::: "memory"); }
__device__ __forceinline__ void cp_wait0()  { asm volatile("cp.async.wait_group 0;" ::: "memory"); }

__device__ __forceinline__ void ldm4(uint32_t* r, uint32_t addr) {
    asm volatile("ldmatrix.sync.aligned.m8n8.x4.shared.b16 {%0,%1,%2,%3}, [%4];"
                 : "=r"(r[0]), "=r"(r[1]), "=r"(r[2]), "=r"(r[3]) : "r"(addr));
}
__device__ __forceinline__ void mma16816(float* d, const uint32_t* a, uint32_t b0, uint32_t b1) {
    asm volatile("mma.sync.aligned.m16n8k16.row.col.f32.f16.f16.f32 "
                 "{%0,%1,%2,%3}, {%4,%5,%6,%7}, {%8,%9}, {%0,%1,%2,%3};"
                 : "+f"(d[0]), "+f"(d[1]), "+f"(d[2]), "+f"(d[3])
                 : "r"(a[0]), "r"(a[1]), "r"(a[2]), "r"(a[3]), "r"(b0), "r"(b1));
}

// ===================== conversion kernels ===================================
__global__ void k_convA(const float* __restrict__ x) {
    int i = blockIdx.x * 256 + threadIdx.x;            // over MM*160 half2
    if (i >= MM * (KPAD / 2)) return;
    int m = i / (KPAD / 2), c2 = i % (KPAD / 2), k = c2 * 2;
    float a = (k < II)     ? x[(size_t)m * II + k]     : 0.f;
    float b = (k + 1 < II) ? x[(size_t)m * II + k + 1] : 0.f;
    ((__half2*)g_xh)[(size_t)m * (KPAD / 2) + c2] = __floats2half2_rn(a, b);
}
__global__ void k_convB(const float* __restrict__ Wf, const float* __restrict__ Wb) {
    int i = blockIdx.x * 256 + threadIdx.x;            // over NPAD*160 half2
    if (i >= NPAD * (KPAD / 2)) return;
    int jg = i / (KPAD / 2), c2 = i % (KPAD / 2), k = c2 * 2;
    int dir = jg >> 9, j = jg & 511;
    const float* W = dir ? Wb : Wf;
    float a = 0.f, b = 0.f;
    if (j < G3) {
        if (k < II)     a = W[(size_t)j * II + k];
        if (k + 1 < II) b = W[(size_t)j * II + k + 1];
    }
    ((__half2*)g_wp)[(size_t)jg * (KPAD / 2) + c2] = __floats2half2_rn(a, b);
}
__global__ void k_convBias(const float* __restrict__ bf, const float* __restrict__ bb) {
    int jg = blockIdx.x * 256 + threadIdx.x;
    if (jg >= NPAD) return;
    int dir = jg >> 9, j = jg & 511;
    g_bihp[jg] = (j < G3) ? (dir ? bb[j] : bf[j]) : 0.f;
}

// ===================== K1: mma.sync GEMM gi = x @ W^T + b ===================
// CTA 128x128, BK=32, double-buffered cp.async. 8 warps: 4(M) x 2(N),
// warp tile 32x64 via m16n8k16 (2 M-frags x 8 N-frags).
#define BM  128
#define BN  128
#define BKC 32
#define LDA 40          // halves per smem row (32 + 8 pad); 80 B, 16B-multiple
#define NSTG (KPAD / BKC)   // 10 k-stages

__global__ void __launch_bounds__(256, 1) k_gemm() {
    __shared__ __align__(16) __half sA[2][BM][LDA];
    __shared__ __align__(16) __half sB[2][BN][LDA];

    const int tid = threadIdx.x, wid = tid >> 5, lane = tid & 31;
    const int wm = wid & 3, wn = wid >> 2;
    const int m0 = blockIdx.x * BM, n0 = blockIdx.y * BN;

    float acc[2][8][4];
#pragma unroll
    for (int mi = 0; mi < 2; mi++)
#pragma unroll
        for (int nj = 0; nj < 8; nj++)
#pragma unroll
            for (int e = 0; e < 4; e++) acc[mi][nj][e] = 0.f;

    const uint32_t sAb[2] = { smem_u32(&sA[0][0][0]), smem_u32(&sA[1][0][0]) };
    const uint32_t sBb[2] = { smem_u32(&sB[0][0][0]), smem_u32(&sB[1][0][0]) };

    auto load_stage = [&](int ks, int buf) {
        int k0 = ks * BKC;
#pragma unroll
        for (int i = 0; i < 2; i++) {
            int idx = tid + i * 256;                  // 512 segs per matrix
            int row = idx >> 2, seg = idx & 3;
            cpasync16(sAb[buf] + (uint32_t)(row * LDA + seg * 8) * 2,
                      g_xh + (size_t)(m0 + row) * KPAD + k0 + seg * 8);
            cpasync16(sBb[buf] + (uint32_t)(row * LDA + seg * 8) * 2,
                      g_wp + (size_t)(n0 + row) * KPAD + k0 + seg * 8);
        }
    };

    load_stage(0, 0); cp_commit();
    load_stage(1, 1); cp_commit();

    // precomputed per-lane intra-tile offsets
    const int a_row = (lane & 15);            // row within 16
    const int a_col8 = (lane >> 4) * 8;       // 0 or 8 halves
    const int b_nrow = ((lane >> 4) * 8) + (lane & 7);   // n within 16
    const int b_col8 = ((lane >> 3) & 1) * 8;            // 0 or 8 halves

    for (int ks = 0; ks < NSTG; ks++) {
        if (ks < NSTG - 1) cp_wait1(); else cp_wait0();
        __syncthreads();
        int buf = ks & 1;
#pragma unroll
        for (int s = 0; s < 2; s++) {                // two k16 steps per stage
            uint32_t a[2][4], bfr[4][4];
#pragma unroll
            for (int mi = 0; mi < 2; mi++) {
                uint32_t addr = sAb[buf] +
                    (uint32_t)(((wm * 32 + mi * 16 + a_row) * LDA) + s * 16 + a_col8) * 2;
                ldm4(a[mi], addr);
            }
#pragma unroll
            for (int nj = 0; nj < 4; nj++) {
                uint32_t addr = sBb[buf] +
                    (uint32_t)(((wn * 64 + nj * 16 + b_nrow) * LDA) + s * 16 + b_col8) * 2;
                ldm4(bfr[nj], addr);
            }
#pragma unroll
            for (int mi = 0; mi < 2; mi++)
#pragma unroll
                for (int nj = 0; nj < 4; nj++) {
                    mma16816(acc[mi][2 * nj],     a[mi], bfr[nj][0], bfr[nj][1]);
                    mma16816(acc[mi][2 * nj + 1], a[mi], bfr[nj][2], bfr[nj][3]);
                }
        }
        __syncthreads();
        if (ks + 2 < NSTG) { load_stage(ks + 2, buf); cp_commit(); }
    }

    // ---- epilogue: bias + scatter to g_gi ----------------------------------
    const int g = lane >> 2, tig = lane & 3;
#pragma unroll
    for (int mi = 0; mi < 2; mi++)
#pragma unroll
        for (int nj = 0; nj < 8; nj++) {
            int coln = wn * 64 + nj * 8 + tig * 2;
            int jglob = n0 + coln;
            int dir = jglob >> 9, jj = jglob & 511;
            if (jj < G3) {
                float bia0 = g_bihp[jglob], bia1 = g_bihp[jglob + 1];
#pragma unroll
                for (int h = 0; h < 2; h++) {        // h=0: row g, h=1: row g+8
                    int m = m0 + wm * 32 + mi * 16 + g + h * 8;
                    int b = m >> 9, t = m & 511;
                    int ts = dir ? (TT - 1 - t) : t;
                    float* p = &g_gi[dir][ts][b][jj];
                    p[0] = acc[mi][nj][2 * h]     + bia0;
                    p[1] = acc[mi][nj][2 * h + 1] + bia1;
                }
            }
        }
}

// ======================= K2: GRU recurrence =================================
__global__ void k_rec(const float* __restrict__ Whh_f, const float* __restrict__ bhh_f,
                      const float* __restrict__ Whh_b, const float* __restrict__ bhh_b)
{
    extern __shared__ char smem[];
    half2* sW   = (half2*)smem;                        // 450*75 half2 = 135000 B
    float* sbhh = (float*)(smem + 135000);             // 456 floats
    float* sh   = sbhh + 456;                          // 2 * 152
    float* sgh  = sh + 2 * 152;                        // 2 * 452
    float* sgin = sgh + 2 * 452;                       // 2 * 152

    int tid  = threadIdx.x;
    int blk  = blockIdx.x;
    int dir  = blk >> 6;
    int pair = blk & 63;
    int b0   = pair * 2;
    const float* Whh = dir ? Whh_b : Whh_f;
    const float* bhh = dir ? bhh_b : bhh_f;

    for (int idx = tid; idx < G3 * 75; idx += blockDim.x) {
        int j = idx / 75, kk = idx % 75;
        sW[j * 75 + kk] = __floats2half2_rn(Whh[j * HH + 2 * kk], Whh[j * HH + 2 * kk + 1]);
    }
    for (int idx = tid; idx < G3; idx += blockDim.x) sbhh[idx] = bhh[idx];
    if (tid < 2 * HH) { int b = tid / HH, jj = tid % HH; sh[b * 152 + jj] = 0.f; }
    __syncthreads();

    const float* gi_base = &g_gi[dir][0][0][0];
    for (int t = 0; t < TT; t++) {
        if (tid < G3) {
            int j = tid;
            long off = ((long)t * BB + b0) * G3 + j;
            float gA = gi_base[off];
            float gB = gi_base[off + G3];
            const half2* wr = sW + j * 75;
            const float2* h0 = (const float2*)(sh);
            const float2* h1 = (const float2*)(sh + 152);
            float acc0 = sbhh[j], acc1 = acc0;
#pragma unroll 15
            for (int kk = 0; kk < 75; kk++) {
                float2 w  = __half22float2(wr[kk]);
                float2 p0 = h0[kk];
                float2 p1 = h1[kk];
                acc0 = fmaf(w.x, p0.x, acc0);
                acc0 = fmaf(w.y, p0.y, acc0);
                acc1 = fmaf(w.x, p1.x, acc1);
                acc1 = fmaf(w.y, p1.y, acc1);
            }
            if (j < 2 * HH) {
                sgh[j]       = acc0 + gA;
                sgh[452 + j] = acc1 + gB;
            } else {
                sgh[j]       = acc0;
                sgh[452 + j] = acc1;
                sgin[j - 2 * HH]       = gA;
                sgin[152 + j - 2 * HH] = gB;
            }
        }
        __syncthreads();
        if (tid < 2 * HH) {
            int b = tid / HH, jj = tid % HH;
            float* ghb = sgh + b * 452;
            float r = 1.f / (1.f + expf(-ghb[jj]));
            float z = 1.f / (1.f + expf(-ghb[jj + HH]));
            float n = tanhf(sgin[b * 152 + jj] + r * ghb[jj + 2 * HH]);
            float hp = sh[b * 152 + jj];
            float hn = (1.f - z) * n + z * hp;
            sh[b * 152 + jj] = hn;
            int tw = dir ? (TT - 1 - t) : t;
            g_seq[b0 + b][tw][dir * HH + jj] = hn;
        }
        __syncthreads();
    }
    if (tid < 2 * HH) {
        int b = tid / HH, jj = tid % HH;
        g_hidden[b0 + b][dir * HH + jj] = sh[b * 152 + jj];
    }
}

// ============== K3a: batch-independent part of attention context ============
__global__ void k_ctxbase(const float* __restrict__ ac, const float* __restrict__ Wattn,
                          const float* __restrict__ battn)
{
    int k = blockIdx.x;
    __shared__ float sac[CC];
    int tid = threadIdx.x;
    if (tid < CC) sac[tid] = ac[k * CC + tid];
    __syncthreads();
    if (tid < D2) {
        float acc = battn[k * D2 + tid];
        const float* W = Wattn + (long)k * (CC + D2) * D2 + tid;
        for (int c = 0; c < CC; c++) acc = fmaf(sac[c], W[(long)c * D2], acc);
        g_ctxbase[k][tid] = acc;
    }
}

// ============== K3b: context = tanh(base + hidden @ Wattn[:,C:,:]) ==========
__global__ void k_context(const float* __restrict__ Wattn)
{
    int k = blockIdx.x, b = blockIdx.y;
    __shared__ float shid[D2];
    int tid = threadIdx.x;
    if (tid < D2) shid[tid] = g_hidden[b][tid];
    __syncthreads();
    if (tid < D2) {
        float acc = g_ctxbase[k][tid];
        const float* W = Wattn + ((long)k * (CC + D2) + CC) * D2 + tid;
        for (int e = 0; e < D2; e++) acc = fmaf(shid[e], W[(long)e * D2], acc);
        g_context[b][k][tid] = tanhf(acc);
    }
}

// ============== K3c: fused attention + topic + classifier + reg part ========
#define TS 16
__global__ void k_attn(const float* __restrict__ Wtop, const float* __restrict__ btop,
                       const float* __restrict__ Wout, const float* __restrict__ bout,
                       float* __restrict__ out)
{
    int b = blockIdx.x;
    __shared__ float sctx[KK][D2];
    __shared__ float sE[TT][KK];
    __shared__ float sSeq[TS][D2];
    __shared__ float spool[KK][D2];
    __shared__ float sfeat[KK * THD];
    __shared__ float sred[256];
    __shared__ float snorm[KK];
    __shared__ float slog[NCLS];
    int tid = threadIdx.x;

    for (int i = tid; i < KK * D2; i += 256) sctx[i / D2][i % D2] = g_context[b][i / D2][i % D2];
    __syncthreads();

    for (int tile = 0; tile < TT / TS; tile++) {
        int t0 = tile * TS;
        for (int i = tid; i < TS * D2; i += 256)
            sSeq[i / D2][i % D2] = g_seq[b][t0 + i / D2][i % D2];
        __syncthreads();
        if (tid < TS * KK) {
            int r = tid / KK, k = tid % KK;
            float acc = 0.f;
            for (int d = 0; d < D2; d++) acc = fmaf(sSeq[r][d], sctx[k][d], acc);
            sE[t0 + r][k] = acc;
        }
        __syncthreads();
    }

    for (int k = 0; k < KK; k++) {
        float m = -1e30f;
        for (int t = tid; t < TT; t += 256) m = fmaxf(m, sE[t][k]);
        sred[tid] = m; __syncthreads();
        for (int s = 128; s > 0; s >>= 1) { if (tid < s) sred[tid] = fmaxf(sred[tid], sred[tid + s]); __syncthreads(); }
        m = sred[0]; __syncthreads();
        float sum = 0.f;
        for (int t = tid; t < TT; t += 256) { float e = expf(sE[t][k] - m); sE[t][k] = e; sum += e; }
        sred[tid] = sum; __syncthreads();
        for (int s = 128; s > 0; s >>= 1) { if (tid < s) sred[tid] += sred[tid + s]; __syncthreads(); }
        float inv = 1.f / sred[0]; __syncthreads();
        for (int t = tid; t < TT; t += 256) sE[t][k] *= inv;
        __syncthreads();
    }

    float pacc[8];
#pragma unroll
    for (int i = 0; i < 8; i++) pacc[i] = 0.f;
    for (int tile = 0; tile < TT / TS; tile++) {
        int t0 = tile * TS;
        for (int i = tid; i < TS * D2; i += 256)
            sSeq[i / D2][i % D2] = g_seq[b][t0 + i / D2][i % D2];
        __syncthreads();
#pragma unroll
        for (int i = 0; i < 8; i++) {
            int idx = tid + i * 256;
            if (idx < KK * D2) {
                int k = idx / D2, d = idx % D2;
                float a = pacc[i];
#pragma unroll
                for (int r = 0; r < TS; r++) a = fmaf(sSeq[r][d], sE[t0 + r][k], a);
                pacc[i] = a;
            }
        }
        __syncthreads();
    }
#pragma unroll
    for (int i = 0; i < 8; i++) {
        int idx = tid + i * 256;
        if (idx < KK * D2) spool[idx / D2][idx % D2] = pacc[i];
    }
    __syncthreads();

    if (tid < KK * THD) {
        int k = tid / THD, hh = tid % THD;
        float acc = btop[k * THD + hh];
        const float* W = Wtop + ((long)k * D2) * THD + hh;
        for (int d = 0; d < D2; d++) acc = fmaf(spool[k][d], W[d * THD], acc);
        sfeat[tid] = fmaxf(acc, 0.f);
    }
    if (tid >= 128 && tid < 128 + KK) {
        int k = tid - 128;
        float s = 0.f;
        for (int d = 0; d < D2; d++) { float v = sctx[k][d]; s = fmaf(v, v, s); }
        snorm[k] = fmaxf(sqrtf(s), 1e-12f);
    }
    __syncthreads();

    if (tid < NCLS) {
        float acc = bout[tid];
        for (int f = 0; f < KK * THD; f++) acc = fmaf(sfeat[f], Wout[f * NCLS + tid], acc);
        slog[tid] = acc;
    }
    if (tid < 64) sred[tid] = 0.f;
    __syncthreads();
    if (tid < KK * KK) {
        int k = tid / KK, j = tid % KK;
        float acc = 0.f;
        for (int d = 0; d < D2; d++) acc = fmaf(sctx[k][d], sctx[j][d], acc);
        acc = acc / (snorm[k] * snorm[j]) - ((k == j) ? 1.f : 0.f);
        sred[tid] = acc * acc;
    }
    __syncthreads();
    if (tid == 0) {
        float m = slog[0];
        for (int c = 1; c < NCLS; c++) m = fmaxf(m, slog[c]);
        float s = 0.f, e[NCLS];
        for (int c = 0; c < NCLS; c++) { e[c] = expf(slog[c] - m); s += e[c]; }
        for (int c = 0; c < NCLS; c++) out[b * NCLS + c] = e[c] / s;
        float rs = 0.f;
        for (int i = 0; i < KK * KK; i++) rs += sred[i];
        g_regpart[b] = sqrtf(rs);
    }
}

// ============== K3d: reg = mean_b regpart =================================
__global__ void k_reg(float* __restrict__ out)
{
    __shared__ float sr[BB];
    int tid = threadIdx.x;
    sr[tid] = g_regpart[tid];
    __syncthreads();
    for (int s = 64; s > 0; s >>= 1) { if (tid < s) sr[tid] += sr[tid + s]; __syncthreads(); }
    if (tid == 0) out[BB * NCLS] = sr[0] / (float)BB;
}

// ===========================================================================
extern "C" void kernel_launch(void* const* d_in, const int* in_sizes, int n_in,
                              void* d_out, int out_size)
{
    const float* x      = (const float*)d_in[0];
    const float* Wih_f  = (const float*)d_in[1];
    const float* Whh_f  = (const float*)d_in[2];
    const float* bih_f  = (const float*)d_in[3];
    const float* bhh_f  = (const float*)d_in[4];
    const float* Wih_b  = (const float*)d_in[5];
    const float* Whh_b  = (const float*)d_in[6];
    const float* bih_b  = (const float*)d_in[7];
    const float* bhh_b  = (const float*)d_in[8];
    const float* ac     = (const float*)d_in[9];
    const float* Wattn  = (const float*)d_in[10];
    const float* battn  = (const float*)d_in[11];
    const float* Wtop   = (const float*)d_in[12];
    const float* btop   = (const float*)d_in[13];
    const float* Wout   = (const float*)d_in[14];
    const float* bout   = (const float*)d_in[15];
    float* out = (float*)d_out;

    cudaFuncSetAttribute(k_rec, cudaFuncAttributeMaxDynamicSharedMemorySize, 146 * 1024);

    k_convA<<<(MM * (KPAD / 2) + 255) / 256, 256>>>(x);
    k_convB<<<(NPAD * (KPAD / 2) + 255) / 256, 256>>>(Wih_f, Wih_b);
    k_convBias<<<(NPAD + 255) / 256, 256>>>(bih_f, bih_b);
    k_gemm<<<dim3(MM / BM, NPAD / BN), 256>>>();
    k_rec<<<128, 480, 142872>>>(Whh_f, bhh_f, Whh_b, bhh_b);
    k_ctxbase<<<KK, 320>>>(ac, Wattn, battn);
    k_context<<<dim3(KK, BB), 320>>>(Wattn);
    k_attn<<<BB, 256>>>(Wtop, btop, Wout, bout, out);
    k_reg<<<1, BB>>>(out);
}

// round 6
// speedup vs baseline: 2.0703x; 1.2880x over previous
#include <cuda_runtime.h>
#include <cuda_fp16.h>
#include <math.h>
#include <stdint.h>

#define BB  128   // batch
#define TT  512   // time
#define II  300   // input dim
#define HH  150   // hidden per dir
#define G3  450   // 3*H
#define KK  6     // topics
#define CC  300   // attn context dim
#define THD 20    // topic hidden
#define NCLS 5
#define D2  300   // 2*H

#define MM    (BB*TT)   // 65536 GEMM rows
#define KPAD  320       // K padded
#define NPAD  1024      // 2 dirs x 512 padded cols

// ---------------- scratch (device globals; no allocations allowed) ----------
__device__ float g_gi[2][TT][BB][G3];     // input projections, [dir][t][b][3H]
__device__ float g_seq[BB][TT][D2];       // bi-GRU outputs
__device__ float g_hidden[BB][D2];        // final hidden states
__device__ float g_ctxbase[KK][D2];       // batch-independent part of context
__device__ float g_context[BB][KK][D2];   // tanh context
__device__ float g_regpart[BB];
__device__ __half g_xh[(size_t)MM * KPAD];   // fp16 x, padded (40 MB)
__device__ __half g_wp[(size_t)NPAD * KPAD]; // fp16 Wih both dirs, padded
__device__ float  g_bihp[NPAD];              // padded bias (both dirs)

// ===================== PTX helpers ==========================================
__device__ __forceinline__ uint32_t smem_u32(const void* p) {
    uint32_t a;
    asm("{ .reg .u64 t; cvta.to.shared.u64 t, %1; cvt.u32.u64 %0, t; }" : "=r"(a) : "l"(p));
    return a;
}
__device__ __forceinline__ void cpasync16(uint32_t dst, const void* src) {
    asm volatile("cp.async.cg.shared.global [%0], [%1], 16;" :: "r"(dst), "l"(src));
}
__device__ __forceinline__ void cp_commit() { asm volatile("cp.async.commit_group;" ::: "memory"); }
__device__ __forceinline__ void cp_wait1()  { asm volatile("cp.async.wait_group 1;" ::: "memory"); }
__device__ __forceinline__ void cp_wait0()  { asm volatile("cp.async.wait_group 0;" ::: "memory"); }

__device__ __forceinline__ void ldm4(uint32_t* r, uint32_t addr) {
    asm volatile("ldmatrix.sync.aligned.m8n8.x4.shared.b16 {%0,%1,%2,%3}, [%4];"
                 : "=r"(r[0]), "=r"(r[1]), "=r"(r[2]), "=r"(r[3]) : "r"(addr));
}
__device__ __forceinline__ void mma16816(float* d, const uint32_t* a, uint32_t b0, uint32_t b1) {
    asm volatile("mma.sync.aligned.m16n8k16.row.col.f32.f16.f16.f32 "
                 "{%0,%1,%2,%3}, {%4,%5,%6,%7}, {%8,%9}, {%0,%1,%2,%3};"
                 : "+f"(d[0]), "+f"(d[1]), "+f"(d[2]), "+f"(d[3])
                 : "r"(a[0]), "r"(a[1]), "r"(a[2]), "r"(a[3]), "r"(b0), "r"(b1));
}
// accurate-enough fast transcendentals (ex2/rcp approx: rel err ~1e-6)
__device__ __forceinline__ float fast_sigmoid(float x) {
    float e, r;
    asm("ex2.approx.f32 %0, %1;" : "=f"(e) : "f"(-1.4426950408889634f * x));
    asm("rcp.approx.f32 %0, %1;" : "=f"(r) : "f"(1.0f + e));
    return r;
}
__device__ __forceinline__ float fast_tanh(float x) {
    float e, r;
    asm("ex2.approx.f32 %0, %1;" : "=f"(e) : "f"(2.8853900817779268f * x));
    asm("rcp.approx.f32 %0, %1;" : "=f"(r) : "f"(1.0f + e));
    return 1.0f - 2.0f * r;
}

// ===================== conversion kernels ===================================
__global__ void k_convA(const float* __restrict__ x) {
    int i = blockIdx.x * 256 + threadIdx.x;            // over MM*160 half2
    if (i >= MM * (KPAD / 2)) return;
    int m = i / (KPAD / 2), c2 = i % (KPAD / 2), k = c2 * 2;
    float a = (k < II)     ? x[(size_t)m * II + k]     : 0.f;
    float b = (k + 1 < II) ? x[(size_t)m * II + k + 1] : 0.f;
    ((__half2*)g_xh)[(size_t)m * (KPAD / 2) + c2] = __floats2half2_rn(a, b);
}
__global__ void k_convB(const float* __restrict__ Wf, const float* __restrict__ Wb) {
    int i = blockIdx.x * 256 + threadIdx.x;            // over NPAD*160 half2
    if (i >= NPAD * (KPAD / 2)) return;
    int jg = i / (KPAD / 2), c2 = i % (KPAD / 2), k = c2 * 2;
    int dir = jg >> 9, j = jg & 511;
    const float* W = dir ? Wb : Wf;
    float a = 0.f, b = 0.f;
    if (j < G3) {
        if (k < II)     a = W[(size_t)j * II + k];
        if (k + 1 < II) b = W[(size_t)j * II + k + 1];
    }
    ((__half2*)g_wp)[(size_t)jg * (KPAD / 2) + c2] = __floats2half2_rn(a, b);
}
__global__ void k_convBias(const float* __restrict__ bf, const float* __restrict__ bb) {
    int jg = blockIdx.x * 256 + threadIdx.x;
    if (jg >= NPAD) return;
    int dir = jg >> 9, j = jg & 511;
    g_bihp[jg] = (j < G3) ? (dir ? bb[j] : bf[j]) : 0.f;
}

// ===================== K1: mma.sync GEMM gi = x @ W^T + b ===================
#define BM  128
#define BN  128
#define BKC 32
#define LDA 40          // halves per smem row (32 + 8 pad); 80 B, 16B-multiple
#define NSTG (KPAD / BKC)   // 10 k-stages

__global__ void __launch_bounds__(256, 2) k_gemm() {
    __shared__ __align__(16) __half sA[2][BM][LDA];
    __shared__ __align__(16) __half sB[2][BN][LDA];

    const int tid = threadIdx.x, wid = tid >> 5, lane = tid & 31;
    const int wm = wid & 3, wn = wid >> 2;
    const int m0 = blockIdx.x * BM, n0 = blockIdx.y * BN;

    float acc[2][8][4];
#pragma unroll
    for (int mi = 0; mi < 2; mi++)
#pragma unroll
        for (int nj = 0; nj < 8; nj++)
#pragma unroll
            for (int e = 0; e < 4; e++) acc[mi][nj][e] = 0.f;

    const uint32_t sAb[2] = { smem_u32(&sA[0][0][0]), smem_u32(&sA[1][0][0]) };
    const uint32_t sBb[2] = { smem_u32(&sB[0][0][0]), smem_u32(&sB[1][0][0]) };

    auto load_stage = [&](int ks, int buf) {
        int k0 = ks * BKC;
#pragma unroll
        for (int i = 0; i < 2; i++) {
            int idx = tid + i * 256;                  // 512 segs per matrix
            int row = idx >> 2, seg = idx & 3;
            cpasync16(sAb[buf] + (uint32_t)(row * LDA + seg * 8) * 2,
                      g_xh + (size_t)(m0 + row) * KPAD + k0 + seg * 8);
            cpasync16(sBb[buf] + (uint32_t)(row * LDA + seg * 8) * 2,
                      g_wp + (size_t)(n0 + row) * KPAD + k0 + seg * 8);
        }
    };

    load_stage(0, 0); cp_commit();
    load_stage(1, 1); cp_commit();

    const int a_row = (lane & 15);
    const int a_col8 = (lane >> 4) * 8;
    const int b_nrow = ((lane >> 4) * 8) + (lane & 7);
    const int b_col8 = ((lane >> 3) & 1) * 8;

    for (int ks = 0; ks < NSTG; ks++) {
        if (ks < NSTG - 1) cp_wait1(); else cp_wait0();
        __syncthreads();
        int buf = ks & 1;
#pragma unroll
        for (int s = 0; s < 2; s++) {
            uint32_t a[2][4], bfr[4][4];
#pragma unroll
            for (int mi = 0; mi < 2; mi++) {
                uint32_t addr = sAb[buf] +
                    (uint32_t)(((wm * 32 + mi * 16 + a_row) * LDA) + s * 16 + a_col8) * 2;
                ldm4(a[mi], addr);
            }
#pragma unroll
            for (int nj = 0; nj < 4; nj++) {
                uint32_t addr = sBb[buf] +
                    (uint32_t)(((wn * 64 + nj * 16 + b_nrow) * LDA) + s * 16 + b_col8) * 2;
                ldm4(bfr[nj], addr);
            }
#pragma unroll
            for (int mi = 0; mi < 2; mi++)
#pragma unroll
                for (int nj = 0; nj < 4; nj++) {
                    mma16816(acc[mi][2 * nj],     a[mi], bfr[nj][0], bfr[nj][1]);
                    mma16816(acc[mi][2 * nj + 1], a[mi], bfr[nj][2], bfr[nj][3]);
                }
        }
        __syncthreads();
        if (ks + 2 < NSTG) { load_stage(ks + 2, buf); cp_commit(); }
    }

    const int g = lane >> 2, tig = lane & 3;
#pragma unroll
    for (int mi = 0; mi < 2; mi++)
#pragma unroll
        for (int nj = 0; nj < 8; nj++) {
            int coln = wn * 64 + nj * 8 + tig * 2;
            int jglob = n0 + coln;
            int dir = jglob >> 9, jj = jglob & 511;
            if (jj < G3) {
                float bia0 = g_bihp[jglob], bia1 = g_bihp[jglob + 1];
#pragma unroll
                for (int h = 0; h < 2; h++) {
                    int m = m0 + wm * 32 + mi * 16 + g + h * 8;
                    int b = m >> 9, t = m & 511;
                    int ts = dir ? (TT - 1 - t) : t;
                    float* p = &g_gi[dir][ts][b][jj];
                    p[0] = acc[mi][nj][2 * h]     + bia0;
                    p[1] = acc[mi][nj][2 * h + 1] + bia1;
                }
            }
        }
}

// ======================= K2: GRU recurrence (HFMA2) =========================
// 128 CTAs: dir*64 + pair; each CTA owns 2 batch rows. Whh fp16 in shared,
// row stride 168 halves (336 B: conflict-free LDS.128). h packed as half2
// (row0,row1) so one HFMA2 serves both rows. fp16 accum chunked every 8
// products with fp32 fixup; z*h_prev path stays fp32 in gate-thread regs.
#define LDW 168
#define SW_BYTES   (G3 * LDW * 2)          // 151200
#define SH2_OFF    SW_BYTES                // half2[160] = 640 B
#define SBHH_OFF   (SH2_OFF + 640)         // float[452]
#define SGH_OFF    (SBHH_OFF + 1808)       // float[2][452]
#define SGIN_OFF   (SGH_OFF + 3616)        // float[2][152]
#define REC_SMEM   (SGIN_OFF + 1216)       // 158480 B

__global__ void k_rec(const float* __restrict__ Whh_f, const float* __restrict__ bhh_f,
                      const float* __restrict__ Whh_b, const float* __restrict__ bhh_b)
{
    extern __shared__ __align__(16) char smem[];
    __half*  sW   = (__half*)smem;
    __half2* sh2  = (__half2*)(smem + SH2_OFF);        // [160] (k-index)
    float*   sbhh = (float*)(smem + SBHH_OFF);
    float*   sgh  = (float*)(smem + SGH_OFF);          // [2][452]
    float*   sgin = (float*)(smem + SGIN_OFF);         // [2][152]

    int tid  = threadIdx.x;
    int blk  = blockIdx.x;
    int dir  = blk >> 6;
    int pair = blk & 63;
    int b0   = pair * 2;
    const float* Whh = dir ? Whh_b : Whh_f;
    const float* bhh = dir ? bhh_b : bhh_f;

    // load weights fp16 (cols 150/151 zero; cols >=152 never read)
    for (int idx = tid; idx < G3 * 152; idx += blockDim.x) {
        int j = idx / 152, k = idx % 152;
        sW[j * LDW + k] = __float2half((k < HH) ? Whh[j * HH + k] : 0.f);
    }
    for (int idx = tid; idx < G3; idx += blockDim.x) sbhh[idx] = bhh[idx];
    if (tid < 160) sh2[tid] = __half2half2(__float2half(0.f));
    float hreg = 0.f;                                  // fp32 h for gate threads
    __syncthreads();

    const float* gi_base = &g_gi[dir][0][0][0];
    for (int t = 0; t < TT; t++) {
        if (tid < G3) {
            int j = tid;
            long off = ((long)t * BB + b0) * G3 + j;
            float gA = gi_base[off];
            float gB = gi_base[off + G3];
            const uint4* wr = (const uint4*)(sW + j * LDW);
            const uint4* hp = (const uint4*)sh2;
            float facc0 = sbhh[j], facc1 = facc0;
#pragma unroll
            for (int g2 = 0; g2 < 19; g2++) {
                uint4 wq = wr[g2];                     // 8 weight halves
                uint4 ha = hp[2 * g2];                 // h2[8g..8g+3]
                uint4 hb = hp[2 * g2 + 1];             // h2[8g+4..8g+7]
                __half2 w01 = *(__half2*)&wq.x, w23 = *(__half2*)&wq.y;
                __half2 w45 = *(__half2*)&wq.z, w67 = *(__half2*)&wq.w;
                __half2 acc = __half2half2(__float2half(0.f));
                acc = __hfma2(__low2half2(w01),  *(__half2*)&ha.x, acc);
                acc = __hfma2(__high2half2(w01), *(__half2*)&ha.y, acc);
                acc = __hfma2(__low2half2(w23),  *(__half2*)&ha.z, acc);
                acc = __hfma2(__high2half2(w23), *(__half2*)&ha.w, acc);
                acc = __hfma2(__low2half2(w45),  *(__half2*)&hb.x, acc);
                acc = __hfma2(__high2half2(w45), *(__half2*)&hb.y, acc);
                acc = __hfma2(__low2half2(w67),  *(__half2*)&hb.z, acc);
                acc = __hfma2(__high2half2(w67), *(__half2*)&hb.w, acc);
                float2 f = __half22float2(acc);
                facc0 += f.x; facc1 += f.y;
            }
            if (j < 2 * HH) {           // r,z gates: gi adds directly
                sgh[j]       = facc0 + gA;
                sgh[452 + j] = facc1 + gB;
            } else {                    // n gate: keep gh and gi_n separate
                sgh[j]       = facc0;
                sgh[452 + j] = facc1;
                sgin[j - 2 * HH]       = gA;
                sgin[152 + j - 2 * HH] = gB;
            }
        }
        __syncthreads();
        if (tid < 2 * HH) {
            int b = tid / HH, jj = tid % HH;
            float* ghb = sgh + b * 452;
            float r = fast_sigmoid(ghb[jj]);
            float z = fast_sigmoid(ghb[jj + HH]);
            float n = fast_tanh(sgin[b * 152 + jj] + r * ghb[jj + 2 * HH]);
            float hn = (1.f - z) * n + z * hreg;
            hreg = hn;
            ((__half*)sh2)[jj * 2 + b] = __float2half(hn);
            int tw = dir ? (TT - 1 - t) : t;
            g_seq[b0 + b][tw][dir * HH + jj] = hn;
        }
        __syncthreads();
    }
    if (tid < 2 * HH) {
        int b = tid / HH, jj = tid % HH;
        g_hidden[b0 + b][dir * HH + jj] = hreg;
    }
}

// ============== K3a: batch-independent part of attention context ============
__global__ void k_ctxbase(const float* __restrict__ ac, const float* __restrict__ Wattn,
                          const float* __restrict__ battn)
{
    int k = blockIdx.x;
    __shared__ float sac[CC];
    int tid = threadIdx.x;
    if (tid < CC) sac[tid] = ac[k * CC + tid];
    __syncthreads();
    if (tid < D2) {
        float acc = battn[k * D2 + tid];
        const float* W = Wattn + (long)k * (CC + D2) * D2 + tid;
        for (int c = 0; c < CC; c++) acc = fmaf(sac[c], W[(long)c * D2], acc);
        g_ctxbase[k][tid] = acc;
    }
}

// ============== K3b: context = tanh(base + hidden @ Wattn[:,C:,:]) ==========
__global__ void k_context(const float* __restrict__ Wattn)
{
    int k = blockIdx.x, b = blockIdx.y;
    __shared__ float shid[D2];
    int tid = threadIdx.x;
    if (tid < D2) shid[tid] = g_hidden[b][tid];
    __syncthreads();
    if (tid < D2) {
        float acc = g_ctxbase[k][tid];
        const float* W = Wattn + ((long)k * (CC + D2) + CC) * D2 + tid;
        for (int e = 0; e < D2; e++) acc = fmaf(shid[e], W[(long)e * D2], acc);
        g_context[b][k][tid] = tanhf(acc);
    }
}

// ============== K3c: fused attention + topic + classifier + reg part ========
#define TS 16
__global__ void k_attn(const float* __restrict__ Wtop, const float* __restrict__ btop,
                       const float* __restrict__ Wout, const float* __restrict__ bout,
                       float* __restrict__ out)
{
    int b = blockIdx.x;
    __shared__ float sctx[KK][D2];
    __shared__ float sE[TT][KK];
    __shared__ float sSeq[TS][D2];
    __shared__ float spool[KK][D2];
    __shared__ float sfeat[KK * THD];
    __shared__ float sred[256];
    __shared__ float snorm[KK];
    __shared__ float slog[NCLS];
    int tid = threadIdx.x;

    for (int i = tid; i < KK * D2; i += 256) sctx[i / D2][i % D2] = g_context[b][i / D2][i % D2];
    __syncthreads();

    for (int tile = 0; tile < TT / TS; tile++) {
        int t0 = tile * TS;
        for (int i = tid; i < TS * D2; i += 256)
            sSeq[i / D2][i % D2] = g_seq[b][t0 + i / D2][i % D2];
        __syncthreads();
        if (tid < TS * KK) {
            int r = tid / KK, k = tid % KK;
            float acc = 0.f;
            for (int d = 0; d < D2; d++) acc = fmaf(sSeq[r][d], sctx[k][d], acc);
            sE[t0 + r][k] = acc;
        }
        __syncthreads();
    }

    for (int k = 0; k < KK; k++) {
        float m = -1e30f;
        for (int t = tid; t < TT; t += 256) m = fmaxf(m, sE[t][k]);
        sred[tid] = m; __syncthreads();
        for (int s = 128; s > 0; s >>= 1) { if (tid < s) sred[tid] = fmaxf(sred[tid], sred[tid + s]); __syncthreads(); }
        m = sred[0]; __syncthreads();
        float sum = 0.f;
        for (int t = tid; t < TT; t += 256) { float e = expf(sE[t][k] - m); sE[t][k] = e; sum += e; }
        sred[tid] = sum; __syncthreads();
        for (int s = 128; s > 0; s >>= 1) { if (tid < s) sred[tid] += sred[tid + s]; __syncthreads(); }
        float inv = 1.f / sred[0]; __syncthreads();
        for (int t = tid; t < TT; t += 256) sE[t][k] *= inv;
        __syncthreads();
    }

    float pacc[8];
#pragma unroll
    for (int i = 0; i < 8; i++) pacc[i] = 0.f;
    for (int tile = 0; tile < TT / TS; tile++) {
        int t0 = tile * TS;
        for (int i = tid; i < TS * D2; i += 256)
            sSeq[i / D2][i % D2] = g_seq[b][t0 + i / D2][i % D2];
        __syncthreads();
#pragma unroll
        for (int i = 0; i < 8; i++) {
            int idx = tid + i * 256;
            if (idx < KK * D2) {
                int k = idx / D2, d = idx % D2;
                float a = pacc[i];
#pragma unroll
                for (int r = 0; r < TS; r++) a = fmaf(sSeq[r][d], sE[t0 + r][k], a);
                pacc[i] = a;
            }
        }
        __syncthreads();
    }
#pragma unroll
    for (int i = 0; i < 8; i++) {
        int idx = tid + i * 256;
        if (idx < KK * D2) spool[idx / D2][idx % D2] = pacc[i];
    }
    __syncthreads();

    if (tid < KK * THD) {
        int k = tid / THD, hh = tid % THD;
        float acc = btop[k * THD + hh];
        const float* W = Wtop + ((long)k * D2) * THD + hh;
        for (int d = 0; d < D2; d++) acc = fmaf(spool[k][d], W[d * THD], acc);
        sfeat[tid] = fmaxf(acc, 0.f);
    }
    if (tid >= 128 && tid < 128 + KK) {
        int k = tid - 128;
        float s = 0.f;
        for (int d = 0; d < D2; d++) { float v = sctx[k][d]; s = fmaf(v, v, s); }
        snorm[k] = fmaxf(sqrtf(s), 1e-12f);
    }
    __syncthreads();

    if (tid < NCLS) {
        float acc = bout[tid];
        for (int f = 0; f < KK * THD; f++) acc = fmaf(sfeat[f], Wout[f * NCLS + tid], acc);
        slog[tid] = acc;
    }
    if (tid < 64) sred[tid] = 0.f;
    __syncthreads();
    if (tid < KK * KK) {
        int k = tid / KK, j = tid % KK;
        float acc = 0.f;
        for (int d = 0; d < D2; d++) acc = fmaf(sctx[k][d], sctx[j][d], acc);
        acc = acc / (snorm[k] * snorm[j]) - ((k == j) ? 1.f : 0.f);
        sred[tid] = acc * acc;
    }
    __syncthreads();
    if (tid == 0) {
        float m = slog[0];
        for (int c = 1; c < NCLS; c++) m = fmaxf(m, slog[c]);
        float s = 0.f, e[NCLS];
        for (int c = 0; c < NCLS; c++) { e[c] = expf(slog[c] - m); s += e[c]; }
        for (int c = 0; c < NCLS; c++) out[b * NCLS + c] = e[c] / s;
        float rs = 0.f;
        for (int i = 0; i < KK * KK; i++) rs += sred[i];
        g_regpart[b] = sqrtf(rs);
    }
}

// ============== K3d: reg = mean_b regpart =================================
__global__ void k_reg(float* __restrict__ out)
{
    __shared__ float sr[BB];
    int tid = threadIdx.x;
    sr[tid] = g_regpart[tid];
    __syncthreads();
    for (int s = 64; s > 0; s >>= 1) { if (tid < s) sr[tid] += sr[tid + s]; __syncthreads(); }
    if (tid == 0) out[BB * NCLS] = sr[0] / (float)BB;
}

// ===========================================================================
extern "C" void kernel_launch(void* const* d_in, const int* in_sizes, int n_in,
                              void* d_out, int out_size)
{
    const float* x      = (const float*)d_in[0];
    const float* Wih_f  = (const float*)d_in[1];
    const float* Whh_f  = (const float*)d_in[2];
    const float* bih_f  = (const float*)d_in[3];
    const float* bhh_f  = (const float*)d_in[4];
    const float* Wih_b  = (const float*)d_in[5];
    const float* Whh_b  = (const float*)d_in[6];
    const float* bih_b  = (const float*)d_in[7];
    const float* bhh_b  = (const float*)d_in[8];
    const float* ac     = (const float*)d_in[9];
    const float* Wattn  = (const float*)d_in[10];
    const float* battn  = (const float*)d_in[11];
    const float* Wtop   = (const float*)d_in[12];
    const float* btop   = (const float*)d_in[13];
    const float* Wout   = (const float*)d_in[14];
    const float* bout   = (const float*)d_in[15];
    float* out = (float*)d_out;

    cudaFuncSetAttribute(k_rec, cudaFuncAttributeMaxDynamicSharedMemorySize, REC_SMEM);

    k_convA<<<(MM * (KPAD / 2) + 255) / 256, 256>>>(x);
    k_convB<<<(NPAD * (KPAD / 2) + 255) / 256, 256>>>(Wih_f, Wih_b);
    k_convBias<<<(NPAD + 255) / 256, 256>>>(bih_f, bih_b);
    k_gemm<<<dim3(MM / BM, NPAD / BN), 256>>>();
    k_rec<<<128, 480, REC_SMEM>>>(Whh_f, bhh_f, Whh_b, bhh_b);
    k_ctxbase<<<KK, 320>>>(ac, Wattn, battn);
    k_context<<<dim3(KK, BB), 320>>>(Wattn);
    k_attn<<<BB, 256>>>(Wtop, btop, Wout, bout, out);
    k_reg<<<1, BB>>>(out);
}

// round 7
// speedup vs baseline: 2.2031x; 1.0642x over previous
#include <cuda_runtime.h>
#include <cuda_fp16.h>
#include <math.h>
#include <stdint.h>

#define BB  128   // batch
#define TT  512   // time
#define II  300   // input dim
#define HH  150   // hidden per dir
#define G3  450   // 3*H
#define KK  6     // topics
#define CC  300   // attn context dim
#define THD 20    // topic hidden
#define NCLS 5
#define D2  300   // 2*H

#define MM    (BB*TT)   // 65536 GEMM rows
#define KPAD  320       // K padded
#define NPAD  1024      // 2 dirs x 512 padded cols

// ---------------- scratch (device globals; no allocations allowed) ----------
__device__ __half g_gih[2][TT][BB][G3];   // input projections fp16 (118 MB)
__device__ float g_seq[BB][TT][D2];       // bi-GRU outputs
__device__ float g_hidden[BB][D2];        // final hidden states
__device__ float g_ctxbase[KK][D2];       // batch-independent part of context
__device__ float g_context[BB][KK][D2];   // tanh context
__device__ float g_regpart[BB];
__device__ __half g_xh[(size_t)MM * KPAD];   // fp16 x, padded (40 MB)
__device__ __half g_wp[(size_t)NPAD * KPAD]; // fp16 Wih both dirs, padded
__device__ float  g_bihp[NPAD];              // padded bias (both dirs)

// ===================== PTX helpers ==========================================
__device__ __forceinline__ uint32_t smem_u32(const void* p) {
    uint32_t a;
    asm("{ .reg .u64 t; cvta.to.shared.u64 t, %1; cvt.u32.u64 %0, t; }" : "=r"(a) : "l"(p));
    return a;
}
__device__ __forceinline__ void cpasync16(uint32_t dst, const void* src) {
    asm volatile("cp.async.cg.shared.global [%0], [%1], 16;" :: "r"(dst), "l"(src));
}
__device__ __forceinline__ void cp_commit() { asm volatile("cp.async.commit_group;" ::: "memory"); }
template<int N> __device__ __forceinline__ void cp_waitg() {
    asm volatile("cp.async.wait_group %0;" :: "n"(N) : "memory");
}
__device__ __forceinline__ void ldm4(uint32_t* r, uint32_t addr) {
    asm volatile("ldmatrix.sync.aligned.m8n8.x4.shared.b16 {%0,%1,%2,%3}, [%4];"
                 : "=r"(r[0]), "=r"(r[1]), "=r"(r[2]), "=r"(r[3]) : "r"(addr));
}
__device__ __forceinline__ void mma16816(float* d, const uint32_t* a, uint32_t b0, uint32_t b1) {
    asm volatile("mma.sync.aligned.m16n8k16.row.col.f32.f16.f16.f32 "
                 "{%0,%1,%2,%3}, {%4,%5,%6,%7}, {%8,%9}, {%0,%1,%2,%3};"
                 : "+f"(d[0]), "+f"(d[1]), "+f"(d[2]), "+f"(d[3])
                 : "r"(a[0]), "r"(a[1]), "r"(a[2]), "r"(a[3]), "r"(b0), "r"(b1));
}
__device__ __forceinline__ float fast_sigmoid(float x) {
    float e, r;
    asm("ex2.approx.f32 %0, %1;" : "=f"(e) : "f"(-1.4426950408889634f * x));
    asm("rcp.approx.f32 %0, %1;" : "=f"(r) : "f"(1.0f + e));
    return r;
}
__device__ __forceinline__ float fast_tanh(float x) {
    float e, r;
    asm("ex2.approx.f32 %0, %1;" : "=f"(e) : "f"(2.8853900817779268f * x));
    asm("rcp.approx.f32 %0, %1;" : "=f"(r) : "f"(1.0f + e));
    return 1.0f - 2.0f * r;
}

// ===================== conversion kernels ===================================
__global__ void k_convA(const float* __restrict__ x) {
    int i = blockIdx.x * 256 + threadIdx.x;
    if (i >= MM * (KPAD / 2)) return;
    int m = i / (KPAD / 2), c2 = i % (KPAD / 2), k = c2 * 2;
    float a = (k < II)     ? x[(size_t)m * II + k]     : 0.f;
    float b = (k + 1 < II) ? x[(size_t)m * II + k + 1] : 0.f;
    ((__half2*)g_xh)[(size_t)m * (KPAD / 2) + c2] = __floats2half2_rn(a, b);
}
__global__ void k_convB(const float* __restrict__ Wf, const float* __restrict__ Wb) {
    int i = blockIdx.x * 256 + threadIdx.x;
    if (i >= NPAD * (KPAD / 2)) return;
    int jg = i / (KPAD / 2), c2 = i % (KPAD / 2), k = c2 * 2;
    int dir = jg >> 9, j = jg & 511;
    const float* W = dir ? Wb : Wf;
    float a = 0.f, b = 0.f;
    if (j < G3) {
        if (k < II)     a = W[(size_t)j * II + k];
        if (k + 1 < II) b = W[(size_t)j * II + k + 1];
    }
    ((__half2*)g_wp)[(size_t)jg * (KPAD / 2) + c2] = __floats2half2_rn(a, b);
}
__global__ void k_convBias(const float* __restrict__ bf, const float* __restrict__ bb) {
    int jg = blockIdx.x * 256 + threadIdx.x;
    if (jg >= NPAD) return;
    int dir = jg >> 9, j = jg & 511;
    g_bihp[jg] = (j < G3) ? (dir ? bb[j] : bf[j]) : 0.f;
}

// ===================== K1: mma.sync GEMM gi = x @ W^T + b ===================
// CTA 128x128, BK=32, 4-stage cp.async pipeline, one barrier per k-iter.
#define BM  128
#define BN  128
#define BKC 32
#define LDA 40                // halves per smem row (32 + 8 pad)
#define NSTG (KPAD / BKC)     // 10 k-stages
#define PSTG 4                // pipeline depth
#define STG_BYTES ((BM + BN) * LDA * 2)       // 20480 B per stage
#define GEMM_SMEM (PSTG * STG_BYTES)          // 81920 B

__global__ void __launch_bounds__(256, 2) k_gemm() {
    extern __shared__ __align__(16) char gsm[];

    const int tid = threadIdx.x, wid = tid >> 5, lane = tid & 31;
    const int wm = wid & 3, wn = wid >> 2;
    const int m0 = blockIdx.x * BM, n0 = blockIdx.y * BN;

    float acc[2][8][4];
#pragma unroll
    for (int mi = 0; mi < 2; mi++)
#pragma unroll
        for (int nj = 0; nj < 8; nj++)
#pragma unroll
            for (int e = 0; e < 4; e++) acc[mi][nj][e] = 0.f;

    uint32_t sAb[PSTG], sBb[PSTG];
#pragma unroll
    for (int s = 0; s < PSTG; s++) {
        sAb[s] = smem_u32(gsm + s * STG_BYTES);
        sBb[s] = sAb[s] + BM * LDA * 2;
    }

    auto load_stage = [&](int ks, int buf) {
        int k0 = ks * BKC;
#pragma unroll
        for (int i = 0; i < 2; i++) {
            int idx = tid + i * 256;                  // 512 segs per matrix
            int row = idx >> 2, seg = idx & 3;
            cpasync16(sAb[buf] + (uint32_t)(row * LDA + seg * 8) * 2,
                      g_xh + (size_t)(m0 + row) * KPAD + k0 + seg * 8);
            cpasync16(sBb[buf] + (uint32_t)(row * LDA + seg * 8) * 2,
                      g_wp + (size_t)(n0 + row) * KPAD + k0 + seg * 8);
        }
    };

    load_stage(0, 0); cp_commit();
    load_stage(1, 1); cp_commit();
    load_stage(2, 2); cp_commit();

    const int a_row = (lane & 15);
    const int a_col8 = (lane >> 4) * 8;
    const int b_nrow = ((lane >> 4) * 8) + (lane & 7);
    const int b_col8 = ((lane >> 3) & 1) * 8;

#pragma unroll
    for (int ks = 0; ks < NSTG; ks++) {
        if (ks <= NSTG - 3)      cp_waitg<2>();
        else if (ks == NSTG - 2) cp_waitg<1>();
        else                     cp_waitg<0>();
        __syncthreads();                  // stage ks ready; all done with ks-1
        if (ks + 3 < NSTG) { load_stage(ks + 3, (ks + 3) & 3); cp_commit(); }
        int buf = ks & 3;
#pragma unroll
        for (int s = 0; s < 2; s++) {
            uint32_t a[2][4], bfr[4][4];
#pragma unroll
            for (int mi = 0; mi < 2; mi++) {
                uint32_t addr = sAb[buf] +
                    (uint32_t)(((wm * 32 + mi * 16 + a_row) * LDA) + s * 16 + a_col8) * 2;
                ldm4(a[mi], addr);
            }
#pragma unroll
            for (int nj = 0; nj < 4; nj++) {
                uint32_t addr = sBb[buf] +
                    (uint32_t)(((wn * 64 + nj * 16 + b_nrow) * LDA) + s * 16 + b_col8) * 2;
                ldm4(bfr[nj], addr);
            }
#pragma unroll
            for (int mi = 0; mi < 2; mi++)
#pragma unroll
                for (int nj = 0; nj < 4; nj++) {
                    mma16816(acc[mi][2 * nj],     a[mi], bfr[nj][0], bfr[nj][1]);
                    mma16816(acc[mi][2 * nj + 1], a[mi], bfr[nj][2], bfr[nj][3]);
                }
        }
    }

    // ---- epilogue: bias + fp16 scatter to g_gih ----------------------------
    const int g = lane >> 2, tig = lane & 3;
#pragma unroll
    for (int mi = 0; mi < 2; mi++)
#pragma unroll
        for (int nj = 0; nj < 8; nj++) {
            int coln = wn * 64 + nj * 8 + tig * 2;
            int jglob = n0 + coln;
            int dir = jglob >> 9, jj = jglob & 511;
            if (jj < G3) {
                float bia0 = g_bihp[jglob], bia1 = g_bihp[jglob + 1];
#pragma unroll
                for (int h = 0; h < 2; h++) {
                    int m = m0 + wm * 32 + mi * 16 + g + h * 8;
                    int b = m >> 9, t = m & 511;
                    int ts = dir ? (TT - 1 - t) : t;
                    *(__half2*)&g_gih[dir][ts][b][jj] =
                        __floats2half2_rn(acc[mi][nj][2 * h] + bia0,
                                          acc[mi][nj][2 * h + 1] + bia1);
                }
            }
        }
}

// ======================= K2: GRU recurrence (HFMA2) =========================
#define LDW 168
#define SW_BYTES   (G3 * LDW * 2)          // 151200
#define SH2_OFF    SW_BYTES                // half2[160] = 640 B
#define SBHH_OFF   (SH2_OFF + 640)         // float[452]
#define SGH_OFF    (SBHH_OFF + 1808)       // float[2][452]
#define SGIN_OFF   (SGH_OFF + 3616)        // float[2][152]
#define REC_SMEM   (SGIN_OFF + 1216)       // 158480 B

__global__ void k_rec(const float* __restrict__ Whh_f, const float* __restrict__ bhh_f,
                      const float* __restrict__ Whh_b, const float* __restrict__ bhh_b)
{
    extern __shared__ __align__(16) char smem[];
    __half*  sW   = (__half*)smem;
    __half2* sh2  = (__half2*)(smem + SH2_OFF);        // [160] (k-index)
    float*   sbhh = (float*)(smem + SBHH_OFF);
    float*   sgh  = (float*)(smem + SGH_OFF);          // [2][452]
    float*   sgin = (float*)(smem + SGIN_OFF);         // [2][152]

    int tid  = threadIdx.x;
    int blk  = blockIdx.x;
    int dir  = blk >> 6;
    int pair = blk & 63;
    int b0   = pair * 2;
    const float* Whh = dir ? Whh_b : Whh_f;
    const float* bhh = dir ? bhh_b : bhh_f;

    for (int idx = tid; idx < G3 * 152; idx += blockDim.x) {
        int j = idx / 152, k = idx % 152;
        sW[j * LDW + k] = __float2half((k < HH) ? Whh[j * HH + k] : 0.f);
    }
    for (int idx = tid; idx < G3; idx += blockDim.x) sbhh[idx] = bhh[idx];
    if (tid < 160) sh2[tid] = __half2half2(__float2half(0.f));
    float hreg = 0.f;
    __syncthreads();

    const __half* gi_base = &g_gih[dir][0][0][0];
    __half pA, pB;
    if (tid < G3) {                                    // prefetch t=0
        long off0 = (long)b0 * G3 + tid;
        pA = gi_base[off0];
        pB = gi_base[off0 + G3];
    }
    for (int t = 0; t < TT; t++) {
        if (tid < G3) {
            int j = tid;
            float gA = __half2float(pA);
            float gB = __half2float(pB);
            if (t + 1 < TT) {                          // prefetch t+1 (hides LDG)
                long offn = ((long)(t + 1) * BB + b0) * G3 + j;
                pA = gi_base[offn];
                pB = gi_base[offn + G3];
            }
            const uint4* wr = (const uint4*)(sW + j * LDW);
            const uint4* hp = (const uint4*)sh2;
            float facc0 = sbhh[j], facc1 = facc0;
#pragma unroll
            for (int g2 = 0; g2 < 19; g2++) {
                uint4 wq = wr[g2];
                uint4 ha = hp[2 * g2];
                uint4 hb = hp[2 * g2 + 1];
                __half2 w01 = *(__half2*)&wq.x, w23 = *(__half2*)&wq.y;
                __half2 w45 = *(__half2*)&wq.z, w67 = *(__half2*)&wq.w;
                __half2 acc = __half2half2(__float2half(0.f));
                acc = __hfma2(__low2half2(w01),  *(__half2*)&ha.x, acc);
                acc = __hfma2(__high2half2(w01), *(__half2*)&ha.y, acc);
                acc = __hfma2(__low2half2(w23),  *(__half2*)&ha.z, acc);
                acc = __hfma2(__high2half2(w23), *(__half2*)&ha.w, acc);
                acc = __hfma2(__low2half2(w45),  *(__half2*)&hb.x, acc);
                acc = __hfma2(__high2half2(w45), *(__half2*)&hb.y, acc);
                acc = __hfma2(__low2half2(w67),  *(__half2*)&hb.z, acc);
                acc = __hfma2(__high2half2(w67), *(__half2*)&hb.w, acc);
                float2 f = __half22float2(acc);
                facc0 += f.x; facc1 += f.y;
            }
            if (j < 2 * HH) {
                sgh[j]       = facc0 + gA;
                sgh[452 + j] = facc1 + gB;
            } else {
                sgh[j]       = facc0;
                sgh[452 + j] = facc1;
                sgin[j - 2 * HH]       = gA;
                sgin[152 + j - 2 * HH] = gB;
            }
        }
        __syncthreads();
        if (tid < 2 * HH) {
            int b = tid / HH, jj = tid % HH;
            float* ghb = sgh + b * 452;
            float r = fast_sigmoid(ghb[jj]);
            float z = fast_sigmoid(ghb[jj + HH]);
            float n = fast_tanh(sgin[b * 152 + jj] + r * ghb[jj + 2 * HH]);
            float hn = (1.f - z) * n + z * hreg;
            hreg = hn;
            ((__half*)sh2)[jj * 2 + b] = __float2half(hn);
            int tw = dir ? (TT - 1 - t) : t;
            g_seq[b0 + b][tw][dir * HH + jj] = hn;
        }
        __syncthreads();
    }
    if (tid < 2 * HH) {
        int b = tid / HH, jj = tid % HH;
        g_hidden[b0 + b][dir * HH + jj] = hreg;
    }
}

// ============== K3a: batch-independent part of attention context ============
__global__ void k_ctxbase(const float* __restrict__ ac, const float* __restrict__ Wattn,
                          const float* __restrict__ battn)
{
    int k = blockIdx.x;
    __shared__ float sac[CC];
    int tid = threadIdx.x;
    if (tid < CC) sac[tid] = ac[k * CC + tid];
    __syncthreads();
    if (tid < D2) {
        float acc = battn[k * D2 + tid];
        const float* W = Wattn + (long)k * (CC + D2) * D2 + tid;
        for (int c = 0; c < CC; c++) acc = fmaf(sac[c], W[(long)c * D2], acc);
        g_ctxbase[k][tid] = acc;
    }
}

// ============== K3b: context = tanh(base + hidden @ Wattn[:,C:,:]) ==========
__global__ void k_context(const float* __restrict__ Wattn)
{
    int k = blockIdx.x, b = blockIdx.y;
    __shared__ float shid[D2];
    int tid = threadIdx.x;
    if (tid < D2) shid[tid] = g_hidden[b][tid];
    __syncthreads();
    if (tid < D2) {
        float acc = g_ctxbase[k][tid];
        const float* W = Wattn + ((long)k * (CC + D2) + CC) * D2 + tid;
        for (int e = 0; e < D2; e++) acc = fmaf(shid[e], W[(long)e * D2], acc);
        g_context[b][k][tid] = tanhf(acc);
    }
}

// ============== K3c: fused attention + topic + classifier + reg part ========
#define TS 16
__global__ void k_attn(const float* __restrict__ Wtop, const float* __restrict__ btop,
                       const float* __restrict__ Wout, const float* __restrict__ bout,
                       float* __restrict__ out)
{
    int b = blockIdx.x;
    __shared__ float sctx[KK][D2];
    __shared__ float sE[TT][KK];
    __shared__ float sSeq[TS][D2];
    __shared__ float spool[KK][D2];
    __shared__ float sfeat[KK * THD];
    __shared__ float sred[256];
    __shared__ float snorm[KK];
    __shared__ float slog[NCLS];
    int tid = threadIdx.x;

    for (int i = tid; i < KK * D2; i += 256) sctx[i / D2][i % D2] = g_context[b][i / D2][i % D2];
    __syncthreads();

    for (int tile = 0; tile < TT / TS; tile++) {
        int t0 = tile * TS;
        for (int i = tid; i < TS * D2; i += 256)
            sSeq[i / D2][i % D2] = g_seq[b][t0 + i / D2][i % D2];
        __syncthreads();
        if (tid < TS * KK) {
            int r = tid / KK, k = tid % KK;
            float acc = 0.f;
            for (int d = 0; d < D2; d++) acc = fmaf(sSeq[r][d], sctx[k][d], acc);
            sE[t0 + r][k] = acc;
        }
        __syncthreads();
    }

    for (int k = 0; k < KK; k++) {
        float m = -1e30f;
        for (int t = tid; t < TT; t += 256) m = fmaxf(m, sE[t][k]);
        sred[tid] = m; __syncthreads();
        for (int s = 128; s > 0; s >>= 1) { if (tid < s) sred[tid] = fmaxf(sred[tid], sred[tid + s]); __syncthreads(); }
        m = sred[0]; __syncthreads();
        float sum = 0.f;
        for (int t = tid; t < TT; t += 256) { float e = expf(sE[t][k] - m); sE[t][k] = e; sum += e; }
        sred[tid] = sum; __syncthreads();
        for (int s = 128; s > 0; s >>= 1) { if (tid < s) sred[tid] += sred[tid + s]; __syncthreads(); }
        float inv = 1.f / sred[0]; __syncthreads();
        for (int t = tid; t < TT; t += 256) sE[t][k] *= inv;
        __syncthreads();
    }

    float pacc[8];
#pragma unroll
    for (int i = 0; i < 8; i++) pacc[i] = 0.f;
    for (int tile = 0; tile < TT / TS; tile++) {
        int t0 = tile * TS;
        for (int i = tid; i < TS * D2; i += 256)
            sSeq[i / D2][i % D2] = g_seq[b][t0 + i / D2][i % D2];
        __syncthreads();
#pragma unroll
        for (int i = 0; i < 8; i++) {
            int idx = tid + i * 256;
            if (idx < KK * D2) {
                int k = idx / D2, d = idx % D2;
                float a = pacc[i];
#pragma unroll
                for (int r = 0; r < TS; r++) a = fmaf(sSeq[r][d], sE[t0 + r][k], a);
                pacc[i] = a;
            }
        }
        __syncthreads();
    }
#pragma unroll
    for (int i = 0; i < 8; i++) {
        int idx = tid + i * 256;
        if (idx < KK * D2) spool[idx / D2][idx % D2] = pacc[i];
    }
    __syncthreads();

    if (tid < KK * THD) {
        int k = tid / THD, hh = tid % THD;
        float acc = btop[k * THD + hh];
        const float* W = Wtop + ((long)k * D2) * THD + hh;
        for (int d = 0; d < D2; d++) acc = fmaf(spool[k][d], W[d * THD], acc);
        sfeat[tid] = fmaxf(acc, 0.f);
    }
    if (tid >= 128 && tid < 128 + KK) {
        int k = tid - 128;
        float s = 0.f;
        for (int d = 0; d < D2; d++) { float v = sctx[k][d]; s = fmaf(v, v, s); }
        snorm[k] = fmaxf(sqrtf(s), 1e-12f);
    }
    __syncthreads();

    if (tid < NCLS) {
        float acc = bout[tid];
        for (int f = 0; f < KK * THD; f++) acc = fmaf(sfeat[f], Wout[f * NCLS + tid], acc);
        slog[tid] = acc;
    }
    if (tid < 64) sred[tid] = 0.f;
    __syncthreads();
    if (tid < KK * KK) {
        int k = tid / KK, j = tid % KK;
        float acc = 0.f;
        for (int d = 0; d < D2; d++) acc = fmaf(sctx[k][d], sctx[j][d], acc);
        acc = acc / (snorm[k] * snorm[j]) - ((k == j) ? 1.f : 0.f);
        sred[tid] = acc * acc;
    }
    __syncthreads();
    if (tid == 0) {
        float m = slog[0];
        for (int c = 1; c < NCLS; c++) m = fmaxf(m, slog[c]);
        float s = 0.f, e[NCLS];
        for (int c = 0; c < NCLS; c++) { e[c] = expf(slog[c] - m); s += e[c]; }
        for (int c = 0; c < NCLS; c++) out[b * NCLS + c] = e[c] / s;
        float rs = 0.f;
        for (int i = 0; i < KK * KK; i++) rs += sred[i];
        g_regpart[b] = sqrtf(rs);
    }
}

// ============== K3d: reg = mean_b regpart =================================
__global__ void k_reg(float* __restrict__ out)
{
    __shared__ float sr[BB];
    int tid = threadIdx.x;
    sr[tid] = g_regpart[tid];
    __syncthreads();
    for (int s = 64; s > 0; s >>= 1) { if (tid < s) sr[tid] += sr[tid + s]; __syncthreads(); }
    if (tid == 0) out[BB * NCLS] = sr[0] / (float)BB;
}

// ===========================================================================
extern "C" void kernel_launch(void* const* d_in, const int* in_sizes, int n_in,
                              void* d_out, int out_size)
{
    const float* x      = (const float*)d_in[0];
    const float* Wih_f  = (const float*)d_in[1];
    const float* Whh_f  = (const float*)d_in[2];
    const float* bih_f  = (const float*)d_in[3];
    const float* bhh_f  = (const float*)d_in[4];
    const float* Wih_b  = (const float*)d_in[5];
    const float* Whh_b  = (const float*)d_in[6];
    const float* bih_b  = (const float*)d_in[7];
    const float* bhh_b  = (const float*)d_in[8];
    const float* ac     = (const float*)d_in[9];
    const float* Wattn  = (const float*)d_in[10];
    const float* battn  = (const float*)d_in[11];
    const float* Wtop   = (const float*)d_in[12];
    const float* btop   = (const float*)d_in[13];
    const float* Wout   = (const float*)d_in[14];
    const float* bout   = (const float*)d_in[15];
    float* out = (float*)d_out;

    cudaFuncSetAttribute(k_rec,  cudaFuncAttributeMaxDynamicSharedMemorySize, REC_SMEM);
    cudaFuncSetAttribute(k_gemm, cudaFuncAttributeMaxDynamicSharedMemorySize, GEMM_SMEM);

    k_convA<<<(MM * (KPAD / 2) + 255) / 256, 256>>>(x);
    k_convB<<<(NPAD * (KPAD / 2) + 255) / 256, 256>>>(Wih_f, Wih_b);
    k_convBias<<<(NPAD + 255) / 256, 256>>>(bih_f, bih_b);
    k_gemm<<<dim3(MM / BM, NPAD / BN), 256, GEMM_SMEM>>>();
    k_rec<<<128, 480, REC_SMEM>>>(Whh_f, bhh_f, Whh_b, bhh_b);
    k_ctxbase<<<KK, 320>>>(ac, Wattn, battn);
    k_context<<<dim3(KK, BB), 320>>>(Wattn);
    k_attn<<<BB, 256>>>(Wtop, btop, Wout, bout, out);
    k_reg<<<1, BB>>>(out);
}

// round 11
// speedup vs baseline: 3.2428x; 1.4719x over previous
#include <cuda_runtime.h>
#include <cuda_fp16.h>
#include <math.h>
#include <stdint.h>

#define BB  128   // batch
#define TT  512   // time
#define II  300   // input dim
#define HH  150   // hidden per dir
#define G3  450   // 3*H
#define KK  6     // topics
#define CC  300   // attn context dim
#define THD 20    // topic hidden
#define NCLS 5
#define D2  300   // 2*H

#define MM    (BB*TT)   // 65536 GEMM rows
#define KPAD  320       // K padded
#define NPAD  1024      // 2 dirs x 512 padded cols

// ---------------- scratch (device globals; no allocations allowed) ----------
__device__ __half g_gih[2][TT][BB][G3];   // input projections fp16 (118 MB)
__device__ float g_seq[BB][TT][D2];       // bi-GRU outputs
__device__ float g_hidden[BB][D2];        // final hidden states
__device__ float g_ctxbase[KK][D2];       // batch-independent part of context
__device__ float g_context[BB][KK][D2];   // tanh context
__device__ float g_regpart[BB];
__device__ __half g_xh[(size_t)MM * KPAD];   // fp16 x, padded (40 MB)
__device__ __half g_wp[(size_t)NPAD * KPAD]; // fp16 Wih both dirs, padded
__device__ float  g_bihp[NPAD];              // padded bias (both dirs)

// ===================== PTX helpers ==========================================
__device__ __forceinline__ uint32_t smem_u32(const void* p) {
    uint32_t a;
    asm("{ .reg .u64 t; cvta.to.shared.u64 t, %1; cvt.u32.u64 %0, t; }" : "=r"(a) : "l"(p));
    return a;
}
__device__ __forceinline__ void cpasync16(uint32_t dst, const void* src) {
    asm volatile("cp.async.cg.shared.global [%0], [%1], 16;" :: "r"(dst), "l"(src));
}
__device__ __forceinline__ void cp_commit() { asm volatile("cp.async.commit_group;" ::: "memory"); }
template<int N> __device__ __forceinline__ void cp_waitg() {
    asm volatile("cp.async.wait_group %0;" :: "n"(N) : "memory");
}
__device__ __forceinline__ void ldm4(uint32_t* r, uint32_t addr) {
    asm volatile("ldmatrix.sync.aligned.m8n8.x4.shared.b16 {%0,%1,%2,%3}, [%4];"
                 : "=r"(r[0]), "=r"(r[1]), "=r"(r[2]), "=r"(r[3]) : "r"(addr));
}
__device__ __forceinline__ void ldm2(uint32_t* r, uint32_t addr) {
    asm volatile("ldmatrix.sync.aligned.m8n8.x2.shared.b16 {%0,%1}, [%2];"
                 : "=r"(r[0]), "=r"(r[1]) : "r"(addr));
}
__device__ __forceinline__ void mma16816(float* d, const uint32_t* a, uint32_t b0, uint32_t b1) {
    asm volatile("mma.sync.aligned.m16n8k16.row.col.f32.f16.f16.f32 "
                 "{%0,%1,%2,%3}, {%4,%5,%6,%7}, {%8,%9}, {%0,%1,%2,%3};"
                 : "+f"(d[0]), "+f"(d[1]), "+f"(d[2]), "+f"(d[3])
                 : "r"(a[0]), "r"(a[1]), "r"(a[2]), "r"(a[3]), "r"(b0), "r"(b1));
}
__device__ __forceinline__ float fast_sigmoid(float x) {
    float e, r;
    asm("ex2.approx.f32 %0, %1;" : "=f"(e) : "f"(-1.4426950408889634f * x));
    asm("rcp.approx.f32 %0, %1;" : "=f"(r) : "f"(1.0f + e));
    return r;
}
__device__ __forceinline__ float fast_tanh(float x) {
    float e, r;
    asm("ex2.approx.f32 %0, %1;" : "=f"(e) : "f"(2.8853900817779268f * x));
    asm("rcp.approx.f32 %0, %1;" : "=f"(r) : "f"(1.0f + e));
    return 1.0f - 2.0f * r;
}

// ===================== conversion kernels ===================================
__global__ void k_convA(const float* __restrict__ x) {
    int i = blockIdx.x * 256 + threadIdx.x;
    if (i >= MM * (KPAD / 2)) return;
    int m = i / (KPAD / 2), c2 = i % (KPAD / 2), k = c2 * 2;
    float a = (k < II)     ? x[(size_t)m * II + k]     : 0.f;
    float b = (k + 1 < II) ? x[(size_t)m * II + k + 1] : 0.f;
    ((__half2*)g_xh)[(size_t)m * (KPAD / 2) + c2] = __floats2half2_rn(a, b);
}
__global__ void k_convB(const float* __restrict__ Wf, const float* __restrict__ Wb) {
    int i = blockIdx.x * 256 + threadIdx.x;
    if (i >= NPAD * (KPAD / 2)) return;
    int jg = i / (KPAD / 2), c2 = i % (KPAD / 2), k = c2 * 2;
    int dir = jg >> 9, j = jg & 511;
    const float* W = dir ? Wb : Wf;
    float a = 0.f, b = 0.f;
    if (j < G3) {
        if (k < II)     a = W[(size_t)j * II + k];
        if (k + 1 < II) b = W[(size_t)j * II + k + 1];
    }
    ((__half2*)g_wp)[(size_t)jg * (KPAD / 2) + c2] = __floats2half2_rn(a, b);
}
__global__ void k_convBias(const float* __restrict__ bf, const float* __restrict__ bb) {
    int jg = blockIdx.x * 256 + threadIdx.x;
    if (jg >= NPAD) return;
    int dir = jg >> 9, j = jg & 511;
    g_bihp[jg] = (j < G3) ? (dir ? bb[j] : bf[j]) : 0.f;
}

// ===================== K1: mma.sync GEMM gi = x @ W^T + b ===================
#define BM  128
#define BN  128
#define BKC 32
#define LDA 40                // halves per smem row (32 + 8 pad)
#define NSTG (KPAD / BKC)     // 10 k-stages
#define PSTG 4                // pipeline depth
#define STG_BYTES ((BM + BN) * LDA * 2)       // 20480 B per stage
#define GEMM_SMEM (PSTG * STG_BYTES)          // 81920 B

__global__ void __launch_bounds__(256, 2) k_gemm() {
    extern __shared__ __align__(16) char gsm[];

    const int tid = threadIdx.x, wid = tid >> 5, lane = tid & 31;
    const int wm = wid & 3, wn = wid >> 2;
    const int m0 = blockIdx.x * BM, n0 = blockIdx.y * BN;

    float acc[2][8][4];
#pragma unroll
    for (int mi = 0; mi < 2; mi++)
#pragma unroll
        for (int nj = 0; nj < 8; nj++)
#pragma unroll
            for (int e = 0; e < 4; e++) acc[mi][nj][e] = 0.f;

    uint32_t sAb[PSTG], sBb[PSTG];
#pragma unroll
    for (int s = 0; s < PSTG; s++) {
        sAb[s] = smem_u32(gsm + s * STG_BYTES);
        sBb[s] = sAb[s] + BM * LDA * 2;
    }

    auto load_stage = [&](int ks, int buf) {
        int k0 = ks * BKC;
#pragma unroll
        for (int i = 0; i < 2; i++) {
            int idx = tid + i * 256;
            int row = idx >> 2, seg = idx & 3;
            cpasync16(sAb[buf] + (uint32_t)(row * LDA + seg * 8) * 2,
                      g_xh + (size_t)(m0 + row) * KPAD + k0 + seg * 8);
            cpasync16(sBb[buf] + (uint32_t)(row * LDA + seg * 8) * 2,
                      g_wp + (size_t)(n0 + row) * KPAD + k0 + seg * 8);
        }
    };

    load_stage(0, 0); cp_commit();
    load_stage(1, 1); cp_commit();
    load_stage(2, 2); cp_commit();

    const int a_row = (lane & 15);
    const int a_col8 = (lane >> 4) * 8;
    const int b_nrow = ((lane >> 4) * 8) + (lane & 7);
    const int b_col8 = ((lane >> 3) & 1) * 8;

#pragma unroll
    for (int ks = 0; ks < NSTG; ks++) {
        if (ks <= NSTG - 3)      cp_waitg<2>();
        else if (ks == NSTG - 2) cp_waitg<1>();
        else                     cp_waitg<0>();
        __syncthreads();
        if (ks + 3 < NSTG) { load_stage(ks + 3, (ks + 3) & 3); cp_commit(); }
        int buf = ks & 3;
#pragma unroll
        for (int s = 0; s < 2; s++) {
            uint32_t a[2][4], bfr[4][4];
#pragma unroll
            for (int mi = 0; mi < 2; mi++) {
                uint32_t addr = sAb[buf] +
                    (uint32_t)(((wm * 32 + mi * 16 + a_row) * LDA) + s * 16 + a_col8) * 2;
                ldm4(a[mi], addr);
            }
#pragma unroll
            for (int nj = 0; nj < 4; nj++) {
                uint32_t addr = sBb[buf] +
                    (uint32_t)(((wn * 64 + nj * 16 + b_nrow) * LDA) + s * 16 + b_col8) * 2;
                ldm4(bfr[nj], addr);
            }
#pragma unroll
            for (int mi = 0; mi < 2; mi++)
#pragma unroll
                for (int nj = 0; nj < 4; nj++) {
                    mma16816(acc[mi][2 * nj],     a[mi], bfr[nj][0], bfr[nj][1]);
                    mma16816(acc[mi][2 * nj + 1], a[mi], bfr[nj][2], bfr[nj][3]);
                }
        }
    }

    const int g = lane >> 2, tig = lane & 3;
#pragma unroll
    for (int mi = 0; mi < 2; mi++)
#pragma unroll
        for (int nj = 0; nj < 8; nj++) {
            int coln = wn * 64 + nj * 8 + tig * 2;
            int jglob = n0 + coln;
            int dir = jglob >> 9, jj = jglob & 511;
            if (jj < G3) {
                float bia0 = g_bihp[jglob], bia1 = g_bihp[jglob + 1];
#pragma unroll
                for (int h = 0; h < 2; h++) {
                    int m = m0 + wm * 32 + mi * 16 + g + h * 8;
                    int b = m >> 9, t = m & 511;
                    int ts = dir ? (TT - 1 - t) : t;
                    *(__half2*)&g_gih[dir][ts][b][jj] =
                        __floats2half2_rn(acc[mi][nj][2 * h] + bia0,
                                          acc[mi][nj][2 * h + 1] + bia1);
                }
            }
        }
}

// ======================= K2: GRU recurrence (tensor-core) ===================
// 128 CTAs (dir*64 + pair), 480 threads = 15 warps. Warp w owns output rows
// [32w, 32w+32) as register-resident mma A-fragments (2 m-tiles x 10 k-tiles).
// Per step: h (8x168 fp16 smem, rows=batch padded to 8) -> 10 ldmatrix.x2 +
// 20 mma.sync with bias-initialized accumulators; lanes with lane%4==0 scatter
// gh cols 0,1 (the two live batch rows) to smem; gate threads finish.
#define RROWS 480                 // 15 warps * 32 rows (450 live)
#define LDS_W 168                 // halves per staging row
#define WSTG_BYTES (RROWS * LDS_W * 2)        // 161280
#define RH_OFF   WSTG_BYTES                   // h: 8 x 168 halves = 2688 B
#define RGH_OFF  (RH_OFF + 2688)              // gh: 2 x 480 floats = 3840 B
#define REC_SMEM (RGH_OFF + 3840)             // 167808 B

__global__ void __launch_bounds__(480, 1) k_rec(
    const float* __restrict__ Whh_f, const float* __restrict__ bhh_f,
    const float* __restrict__ Whh_b, const float* __restrict__ bhh_b)
{
    extern __shared__ __align__(16) char smem[];
    __half* sWst = (__half*)smem;                       // staging (init only)
    __half* sh   = (__half*)(smem + RH_OFF);            // [8][168]
    float*  sgh  = (float*)(smem + RGH_OFF);            // [2][480]

    const int tid  = threadIdx.x, wid = tid >> 5, lane = tid & 31;
    const int blk  = blockIdx.x;
    const int dir  = blk >> 6;
    const int b0   = (blk & 63) * 2;
    const float* Whh = dir ? Whh_b : Whh_f;
    const float* bhh = dir ? bhh_b : bhh_f;

    // ---- init: stage Whh fp16 padded [480][168], zero h ----
    for (int idx = tid; idx < RROWS * LDS_W; idx += 480) {
        int j = idx / LDS_W, k = idx - j * LDS_W;
        sWst[j * LDS_W + k] = __float2half(
            (j < G3 && k < HH) ? Whh[j * HH + k] : 0.f);
    }
    for (int idx = tid; idx < 8 * LDS_W; idx += 480)
        sh[idx] = __float2half(0.f);
    __syncthreads();

    // ---- load A fragments into registers (once) ----
    const int a_row = lane & 15, a_col8 = (lane >> 4) * 8;
    uint32_t afr[2][10][4];
#pragma unroll
    for (int mt = 0; mt < 2; mt++)
#pragma unroll
        for (int kt = 0; kt < 10; kt++) {
            uint32_t addr = smem_u32(sWst) +
                (uint32_t)(((wid * 32 + mt * 16 + a_row) * LDS_W) + kt * 16 + a_col8) * 2;
            ldm4(afr[mt][kt], addr);
        }

    // bias registers for accumulator init (rows g, g+8 per m-tile)
    const int g = lane >> 2;
    float bias[2][2];
#pragma unroll
    for (int mt = 0; mt < 2; mt++) {
        int r = wid * 32 + mt * 16 + g;
        bias[mt][0] = (r < G3) ? bhh[r] : 0.f;
        bias[mt][1] = (r + 8 < G3) ? bhh[r + 8] : 0.f;
    }

    // B ldmatrix per-lane base address into h tile
    int hrow = (lane < 8) ? lane : ((lane < 16) ? (lane - 8) : 0);
    int hcol = (lane >= 8 && lane < 16) ? 8 : 0;
    const uint32_t hb = smem_u32(sh) + (uint32_t)(hrow * LDS_W + hcol) * 2;

    __syncthreads();   // A frags loaded; staging smem now dead

    // gi prefetch (gate threads: tid<300 -> (b, jj))
    const __half* gi_base = &g_gih[dir][0][0][0];
    const int gb = tid / HH, gj = tid - gb * HH;       // valid when tid<300
    __half pr, pz, pn;
    float hreg = 0.f;
    if (tid < 2 * HH) {
        long o = (long)(b0 + gb) * G3 + gj;
        pr = gi_base[o]; pz = gi_base[o + HH]; pn = gi_base[o + 2 * HH];
    }

    for (int t = 0; t < TT; t++) {
        // ---- matvec via tensor cores ----
        float acc0[4] = { bias[0][0], bias[0][0], bias[0][1], bias[0][1] };
        float acc1[4] = { bias[1][0], bias[1][0], bias[1][1], bias[1][1] };
#pragma unroll
        for (int kt = 0; kt < 10; kt++) {
            uint32_t bfr[2];
            ldm2(bfr, hb + kt * 32);                   // 16 k-halves, n rows 0-7
            mma16816(acc0, afr[0][kt], bfr[0], bfr[1]);
            mma16816(acc1, afr[1][kt], bfr[0], bfr[1]);
        }
        if ((lane & 3) == 0) {                         // cols 0,1 = batch rows
            int r0 = wid * 32 + g;
            sgh[r0]            = acc0[0]; sgh[480 + r0]      = acc0[1];
            sgh[r0 + 8]        = acc0[2]; sgh[480 + r0 + 8]  = acc0[3];
            sgh[r0 + 16]       = acc1[0]; sgh[480 + r0 + 16] = acc1[1];
            sgh[r0 + 24]       = acc1[2]; sgh[480 + r0 + 24] = acc1[3];
        }
        __syncthreads();                               // gh ready; h reads done

        // ---- gates ----
        if (tid < 2 * HH) {
            float gir = __half2float(pr), giz = __half2float(pz), gin = __half2float(pn);
            if (t + 1 < TT) {                          // prefetch next step
                long o = ((long)(t + 1) * BB + b0 + gb) * G3 + gj;
                pr = gi_base[o]; pz = gi_base[o + HH]; pn = gi_base[o + 2 * HH];
            }
            const float* ghb = sgh + gb * 480;
            float r = fast_sigmoid(ghb[gj] + gir);
            float z = fast_sigmoid(ghb[gj + HH] + giz);
            float n = fast_tanh(gin + r * ghb[gj + 2 * HH]);
            float hn = (1.f - z) * n + z * hreg;
            hreg = hn;
            sh[gb * LDS_W + gj] = __float2half(hn);
            int tw = dir ? (TT - 1 - t) : t;
            g_seq[b0 + gb][tw][dir * HH + gj] = hn;
        }
        __syncthreads();                               // h ready for next step
    }
    if (tid < 2 * HH)
        g_hidden[b0 + gb][dir * HH + gj] = hreg;
}

// ============== K3a: batch-independent part of attention context ============
__global__ void k_ctxbase(const float* __restrict__ ac, const float* __restrict__ Wattn,
                          const float* __restrict__ battn)
{
    int k = blockIdx.x;
    __shared__ float sac[CC];
    int tid = threadIdx.x;
    if (tid < CC) sac[tid] = ac[k * CC + tid];
    __syncthreads();
    if (tid < D2) {
        float acc = battn[k * D2 + tid];
        const float* W = Wattn + (long)k * (CC + D2) * D2 + tid;
        for (int c = 0; c < CC; c++) acc = fmaf(sac[c], W[(long)c * D2], acc);
        g_ctxbase[k][tid] = acc;
    }
}

// ============== K3b: context = tanh(base + hidden @ Wattn[:,C:,:]) ==========
__global__ void k_context(const float* __restrict__ Wattn)
{
    int k = blockIdx.x, b = blockIdx.y;
    __shared__ float shid[D2];
    int tid = threadIdx.x;
    if (tid < D2) shid[tid] = g_hidden[b][tid];
    __syncthreads();
    if (tid < D2) {
        float acc = g_ctxbase[k][tid];
        const float* W = Wattn + ((long)k * (CC + D2) + CC) * D2 + tid;
        for (int e = 0; e < D2; e++) acc = fmaf(shid[e], W[(long)e * D2], acc);
        g_context[b][k][tid] = tanhf(acc);
    }
}

// ============== K3c: fused attention + topic + classifier + reg part ========
#define TS 16
__global__ void k_attn(const float* __restrict__ Wtop, const float* __restrict__ btop,
                       const float* __restrict__ Wout, const float* __restrict__ bout,
                       float* __restrict__ out)
{
    int b = blockIdx.x;
    __shared__ float sctx[KK][D2];
    __shared__ float sE[TT][KK];
    __shared__ float sSeq[TS][D2];
    __shared__ float spool[KK][D2];
    __shared__ float sfeat[KK * THD];
    __shared__ float sred[256];
    __shared__ float snorm[KK];
    __shared__ float slog[NCLS];
    int tid = threadIdx.x;

    for (int i = tid; i < KK * D2; i += 256) sctx[i / D2][i % D2] = g_context[b][i / D2][i % D2];
    __syncthreads();

    for (int tile = 0; tile < TT / TS; tile++) {
        int t0 = tile * TS;
        for (int i = tid; i < TS * D2; i += 256)
            sSeq[i / D2][i % D2] = g_seq[b][t0 + i / D2][i % D2];
        __syncthreads();
        if (tid < TS * KK) {
            int r = tid / KK, k = tid % KK;
            float acc = 0.f;
            for (int d = 0; d < D2; d++) acc = fmaf(sSeq[r][d], sctx[k][d], acc);
            sE[t0 + r][k] = acc;
        }
        __syncthreads();
    }

    for (int k = 0; k < KK; k++) {
        float m = -1e30f;
        for (int t = tid; t < TT; t += 256) m = fmaxf(m, sE[t][k]);
        sred[tid] = m; __syncthreads();
        for (int s = 128; s > 0; s >>= 1) { if (tid < s) sred[tid] = fmaxf(sred[tid], sred[tid + s]); __syncthreads(); }
        m = sred[0]; __syncthreads();
        float sum = 0.f;
        for (int t = tid; t < TT; t += 256) { float e = expf(sE[t][k] - m); sE[t][k] = e; sum += e; }
        sred[tid] = sum; __syncthreads();
        for (int s = 128; s > 0; s >>= 1) { if (tid < s) sred[tid] += sred[tid + s]; __syncthreads(); }
        float inv = 1.f / sred[0]; __syncthreads();
        for (int t = tid; t < TT; t += 256) sE[t][k] *= inv;
        __syncthreads();
    }

    float pacc[8];
#pragma unroll
    for (int i = 0; i < 8; i++) pacc[i] = 0.f;
    for (int tile = 0; tile < TT / TS; tile++) {
        int t0 = tile * TS;
        for (int i = tid; i < TS * D2; i += 256)
            sSeq[i / D2][i % D2] = g_seq[b][t0 + i / D2][i % D2];
        __syncthreads();
#pragma unroll
        for (int i = 0; i < 8; i++) {
            int idx = tid + i * 256;
            if (idx < KK * D2) {
                int k = idx / D2, d = idx % D2;
                float a = pacc[i];
#pragma unroll
                for (int r = 0; r < TS; r++) a = fmaf(sSeq[r][d], sE[t0 + r][k], a);
                pacc[i] = a;
            }
        }
        __syncthreads();
    }
#pragma unroll
    for (int i = 0; i < 8; i++) {
        int idx = tid + i * 256;
        if (idx < KK * D2) spool[idx / D2][idx % D2] = pacc[i];
    }
    __syncthreads();

    if (tid < KK * THD) {
        int k = tid / THD, hh = tid % THD;
        float acc = btop[k * THD + hh];
        const float* W = Wtop + ((long)k * D2) * THD + hh;
        for (int d = 0; d < D2; d++) acc = fmaf(spool[k][d], W[d * THD], acc);
        sfeat[tid] = fmaxf(acc, 0.f);
    }
    if (tid >= 128 && tid < 128 + KK) {
        int k = tid - 128;
        float s = 0.f;
        for (int d = 0; d < D2; d++) { float v = sctx[k][d]; s = fmaf(v, v, s); }
        snorm[k] = fmaxf(sqrtf(s), 1e-12f);
    }
    __syncthreads();

    if (tid < NCLS) {
        float acc = bout[tid];
        for (int f = 0; f < KK * THD; f++) acc = fmaf(sfeat[f], Wout[f * NCLS + tid], acc);
        slog[tid] = acc;
    }
    if (tid < 64) sred[tid] = 0.f;
    __syncthreads();
    if (tid < KK * KK) {
        int k = tid / KK, j = tid % KK;
        float acc = 0.f;
        for (int d = 0; d < D2; d++) acc = fmaf(sctx[k][d], sctx[j][d], acc);
        acc = acc / (snorm[k] * snorm[j]) - ((k == j) ? 1.f : 0.f);
        sred[tid] = acc * acc;
    }
    __syncthreads();
    if (tid == 0) {
        float m = slog[0];
        for (int c = 1; c < NCLS; c++) m = fmaxf(m, slog[c]);
        float s = 0.f, e[NCLS];
        for (int c = 0; c < NCLS; c++) { e[c] = expf(slog[c] - m); s += e[c]; }
        for (int c = 0; c < NCLS; c++) out[b * NCLS + c] = e[c] / s;
        float rs = 0.f;
        for (int i = 0; i < KK * KK; i++) rs += sred[i];
        g_regpart[b] = sqrtf(rs);
    }
}

// ============== K3d: reg = mean_b regpart =================================
__global__ void k_reg(float* __restrict__ out)
{
    __shared__ float sr[BB];
    int tid = threadIdx.x;
    sr[tid] = g_regpart[tid];
    __syncthreads();
    for (int s = 64; s > 0; s >>= 1) { if (tid < s) sr[tid] += sr[tid + s]; __syncthreads(); }
    if (tid == 0) out[BB * NCLS] = sr[0] / (float)BB;
}

// ===========================================================================
extern "C" void kernel_launch(void* const* d_in, const int* in_sizes, int n_in,
                              void* d_out, int out_size)
{
    const float* x      = (const float*)d_in[0];
    const float* Wih_f  = (const float*)d_in[1];
    const float* Whh_f  = (const float*)d_in[2];
    const float* bih_f  = (const float*)d_in[3];
    const float* bhh_f  = (const float*)d_in[4];
    const float* Wih_b  = (const float*)d_in[5];
    const float* Whh_b  = (const float*)d_in[6];
    const float* bih_b  = (const float*)d_in[7];
    const float* bhh_b  = (const float*)d_in[8];
    const float* ac     = (const float*)d_in[9];
    const float* Wattn  = (const float*)d_in[10];
    const float* battn  = (const float*)d_in[11];
    const float* Wtop   = (const float*)d_in[12];
    const float* btop   = (const float*)d_in[13];
    const float* Wout   = (const float*)d_in[14];
    const float* bout   = (const float*)d_in[15];
    float* out = (float*)d_out;

    cudaFuncSetAttribute(k_rec,  cudaFuncAttributeMaxDynamicSharedMemorySize, REC_SMEM);
    cudaFuncSetAttribute(k_gemm, cudaFuncAttributeMaxDynamicSharedMemorySize, GEMM_SMEM);

    k_convA<<<(MM * (KPAD / 2) + 255) / 256, 256>>>(x);
    k_convB<<<(NPAD * (KPAD / 2) + 255) / 256, 256>>>(Wih_f, Wih_b);
    k_convBias<<<(NPAD + 255) / 256, 256>>>(bih_f, bih_b);
    k_gemm<<<dim3(MM / BM, NPAD / BN), 256, GEMM_SMEM>>>();
    k_rec<<<128, 480, REC_SMEM>>>(Whh_f, bhh_f, Whh_b, bhh_b);
    k_ctxbase<<<KK, 320>>>(ac, Wattn, battn);
    k_context<<<dim3(KK, BB), 320>>>(Wattn);
    k_attn<<<BB, 256>>>(Wtop, btop, Wout, bout, out);
    k_reg<<<1, BB>>>(out);
}